// round 12
// baseline (speedup 1.0000x reference)
#include <cuda_runtime.h>
#include <math.h>
#include <stdint.h>

// Problem constants
constexpr int S_LEN = 4096;
constexpr int BATCH = 2;
constexpr int EMB   = 512;   // E and also H*D
constexpr int NH    = 8;
constexpr int DH    = 64;
constexpr int HALF  = 256;   // sliding window half-width
constexpr int ROWS  = BATCH * S_LEN;  // 8192
constexpr int KPR   = EMB / 2;        // 256 kpairs per row

// Scratch (allocation-free rule: __device__ globals)
__device__ uint32_t g_qh[(size_t)ROWS * KPR];
__device__ uint32_t g_ql[(size_t)ROWS * KPR];
__device__ uint32_t g_kh[(size_t)ROWS * KPR];
__device__ uint32_t g_kl[(size_t)ROWS * KPR];
__device__ uint32_t g_vh[(size_t)ROWS * KPR];
__device__ uint32_t g_vl[(size_t)ROWS * KPR];
__device__ float    g_att[(size_t)ROWS * EMB];

// ---------------------------------------------------------------------------
// helpers
// ---------------------------------------------------------------------------
__device__ __forceinline__ void split2(float x0, float x1,
                                       uint32_t& hp, uint32_t& lp) {
    asm("cvt.rn.bf16x2.f32 %0, %1, %2;" : "=r"(hp) : "f"(x1), "f"(x0));
    float h0 = __uint_as_float(hp << 16);
    float h1 = __uint_as_float(hp & 0xffff0000u);
    float r0 = x0 - h0;
    float r1 = x1 - h1;
    asm("cvt.rn.bf16x2.f32 %0, %1, %2;" : "=r"(lp) : "f"(r1), "f"(r0));
}

__device__ __forceinline__ void mma_bf16(float d[4], const uint32_t a[4],
                                         const uint32_t b[2]) {
    asm volatile(
        "mma.sync.aligned.m16n8k16.row.col.f32.bf16.bf16.f32 "
        "{%0,%1,%2,%3}, {%4,%5,%6,%7}, {%8,%9}, {%0,%1,%2,%3};\n"
        : "+f"(d[0]), "+f"(d[1]), "+f"(d[2]), "+f"(d[3])
        : "r"(a[0]), "r"(a[1]), "r"(a[2]), "r"(a[3]), "r"(b[0]), "r"(b[1]));
}

__device__ __forceinline__ void ldsm_x4(uint32_t r[4], uint32_t addr) {
    asm volatile(
        "ldmatrix.sync.aligned.m8n8.x4.shared.b16 {%0,%1,%2,%3}, [%4];"
        : "=r"(r[0]), "=r"(r[1]), "=r"(r[2]), "=r"(r[3]) : "r"(addr));
}

__device__ __forceinline__ uint32_t smem_u32(const void* p) {
    return (uint32_t)__cvta_generic_to_shared(p);
}

__device__ __forceinline__ uint32_t prmt(uint32_t a, uint32_t b, uint32_t s) {
    uint32_t d;
    asm("prmt.b32 %0, %1, %2, %3;" : "=r"(d) : "r"(a), "r"(b), "r"(s));
    return d;
}

// ---------------------------------------------------------------------------
// Split-bf16 tensor-core GEMM, 128x64 CTA tile, 2 CTAs/SM for phase overlap.
// C[M,N] = A[M,K] @ B[K,N], row-major. 256 threads, 8 warps (4m x 2n),
// warp tile 32x32. BK=32 (16 kpairs), double-buffered + register prefetch.
// A smem [m][kp] stride 20; B smem [kp][n] stride 72 (frag bank 8qc+gr
// bijective -> conflict-free).
// SPLIT_OUT=true writes bf16x2 hi/lo planes, else fp32.
// ---------------------------------------------------------------------------
constexpr int GBM = 128, GBN = 64, GBK = 32;
constexpr int KP  = GBK / 2;            // 16
constexpr int ASTR = 20;
constexpr int BSTR = 72;
constexpr int A_STAGE = GBM * ASTR;     // 2560
constexpr int B_STAGE = KP * BSTR;      // 1152
constexpr int GEMM_SMEM_BYTES = (4 * A_STAGE + 4 * B_STAGE) * 4;  // 59392

template <bool SPLIT_OUT>
__global__ __launch_bounds__(256, 2) void gemm_bf16_kernel(
    const float* __restrict__ A, const float* __restrict__ B,
    float* __restrict__ C, uint32_t* __restrict__ Ch, uint32_t* __restrict__ Cl,
    int M, int N, int K)
{
    extern __shared__ uint32_t sm[];
    uint32_t* sAh = sm;
    uint32_t* sAl = sAh + 2 * A_STAGE;
    uint32_t* sBh = sAl + 2 * A_STAGE;
    uint32_t* sBl = sBh + 2 * B_STAGE;

    const int tid  = threadIdx.x;
    const int lane = tid & 31;
    const int wid  = tid >> 5;
    const int m_base = (wid >> 1) * 32;     // 0,32,64,96
    const int n_base = (wid & 1) * 32;      // 0,32
    const int row0 = blockIdx.y * GBM;
    const int col0 = blockIdx.x * GBN;

    // A global mapping: rows arow, arow+64; 8 floats at acolg
    const int arow  = tid >> 2;
    const int acolg = (tid & 3) * 8;
    const int akp   = (tid & 3) * 4;
    // B global mapping: kpair tid>>4 (0..15); 4 cols at bcol
    const int bkp  = tid >> 4;
    const int bcol = (tid & 15) * 4;

    const float* pA0 = A + (size_t)(row0 + arow) * K + acolg;
    const float* pA1 = A + (size_t)(row0 + arow + 64) * K + acolg;
    const float* pB0 = B + (size_t)(2 * bkp) * N + col0 + bcol;
    const float* pB1 = B + (size_t)(2 * bkp + 1) * N + col0 + bcol;

    const int NT = K / GBK;   // 16

    float acc[2][4][4] = {};
    float4 fa00, fa01, fa10, fa11;   // A prefetch (2 rows x 8)
    float4 fb0, fb1;                 // B prefetch (2 k-rows x 4)

    #define STORE_A(dsth, dstl, r, v0, v1)                                    \
        {                                                                     \
            uint32_t h0, l0, h1, l1, h2, l2, h3, l3;                          \
            split2((v0).x, (v0).y, h0, l0);                                   \
            split2((v0).z, (v0).w, h1, l1);                                   \
            split2((v1).x, (v1).y, h2, l2);                                   \
            split2((v1).z, (v1).w, h3, l3);                                   \
            *(uint4*)&(dsth)[(r) * ASTR + akp] = make_uint4(h0, h1, h2, h3);  \
            *(uint4*)&(dstl)[(r) * ASTR + akp] = make_uint4(l0, l1, l2, l3);  \
        }

    #define STORE_B(dsth, dstl, v0, v1)                                       \
        {                                                                     \
            uint32_t h0, l0, h1, l1, h2, l2, h3, l3;                          \
            split2((v0).x, (v1).x, h0, l0);                                   \
            split2((v0).y, (v1).y, h1, l1);                                   \
            split2((v0).z, (v1).z, h2, l2);                                   \
            split2((v0).w, (v1).w, h3, l3);                                   \
            *(uint4*)&(dsth)[bkp * BSTR + bcol] = make_uint4(h0, h1, h2, h3); \
            *(uint4*)&(dstl)[bkp * BSTR + bcol] = make_uint4(l0, l1, l2, l3); \
        }

    fa00 = *(const float4*)(pA0);
    fa01 = *(const float4*)(pA0 + 4);
    fa10 = *(const float4*)(pA1);
    fa11 = *(const float4*)(pA1 + 4);
    fb0  = *(const float4*)(pB0);
    fb1  = *(const float4*)(pB1);

    STORE_A(sAh, sAl, arow, fa00, fa01);
    STORE_A(sAh, sAl, arow + 64, fa10, fa11);
    STORE_B(sBh, sBl, fb0, fb1);
    __syncthreads();

    const int gr = lane >> 2;
    const int qc = lane & 3;

    for (int kt = 0; kt < NT; kt++) {
        if (kt + 1 < NT) {
            int ko = (kt + 1) * GBK;
            fa00 = *(const float4*)(pA0 + ko);
            fa01 = *(const float4*)(pA0 + ko + 4);
            fa10 = *(const float4*)(pA1 + ko);
            fa11 = *(const float4*)(pA1 + ko + 4);
            fb0  = *(const float4*)(pB0 + (size_t)ko * N);
            fb1  = *(const float4*)(pB1 + (size_t)ko * N);
        }

        const uint32_t* Ah = sAh + (kt & 1) * A_STAGE;
        const uint32_t* Al = sAl + (kt & 1) * A_STAGE;
        const uint32_t* Bh = sBh + (kt & 1) * B_STAGE;
        const uint32_t* Bl = sBl + (kt & 1) * B_STAGE;

        #pragma unroll
        for (int ks = 0; ks < 2; ks++) {
            const int kp0 = ks * 8 + qc;
            uint32_t ah[2][4], al[2][4], bh[4][2], bl[4][2];
            #pragma unroll
            for (int mt = 0; mt < 2; mt++) {
                const int m = m_base + mt * 16 + gr;
                ah[mt][0] = Ah[m * ASTR + kp0];
                ah[mt][1] = Ah[(m + 8) * ASTR + kp0];
                ah[mt][2] = Ah[m * ASTR + kp0 + 4];
                ah[mt][3] = Ah[(m + 8) * ASTR + kp0 + 4];
                al[mt][0] = Al[m * ASTR + kp0];
                al[mt][1] = Al[(m + 8) * ASTR + kp0];
                al[mt][2] = Al[m * ASTR + kp0 + 4];
                al[mt][3] = Al[(m + 8) * ASTR + kp0 + 4];
            }
            #pragma unroll
            for (int nt = 0; nt < 4; nt++) {
                const int n = n_base + nt * 8 + gr;
                bh[nt][0] = Bh[kp0 * BSTR + n];
                bh[nt][1] = Bh[(kp0 + 4) * BSTR + n];
                bl[nt][0] = Bl[kp0 * BSTR + n];
                bl[nt][1] = Bl[(kp0 + 4) * BSTR + n];
            }
            #pragma unroll
            for (int mt = 0; mt < 2; mt++)
                #pragma unroll
                for (int nt = 0; nt < 4; nt++) {
                    mma_bf16(acc[mt][nt], ah[mt], bh[nt]);
                    mma_bf16(acc[mt][nt], ah[mt], bl[nt]);
                    mma_bf16(acc[mt][nt], al[mt], bh[nt]);
                }
        }

        if (kt + 1 < NT) {
            uint32_t* dAh = sAh + ((kt + 1) & 1) * A_STAGE;
            uint32_t* dAl = sAl + ((kt + 1) & 1) * A_STAGE;
            uint32_t* dBh = sBh + ((kt + 1) & 1) * B_STAGE;
            uint32_t* dBl = sBl + ((kt + 1) & 1) * B_STAGE;
            STORE_A(dAh, dAl, arow, fa00, fa01);
            STORE_A(dAh, dAl, arow + 64, fa10, fa11);
            STORE_B(dBh, dBl, fb0, fb1);
        }
        __syncthreads();
    }
    #undef STORE_A
    #undef STORE_B

    #pragma unroll
    for (int mt = 0; mt < 2; mt++) {
        #pragma unroll
        for (int nt = 0; nt < 4; nt++) {
            int r = row0 + m_base + mt * 16 + gr;
            int c = col0 + n_base + nt * 8 + 2 * qc;
            if constexpr (SPLIT_OUT) {
                int kp = c >> 1;
                uint32_t hp, lp;
                split2(acc[mt][nt][0], acc[mt][nt][1], hp, lp);
                Ch[(size_t)r * KPR + kp] = hp;
                Cl[(size_t)r * KPR + kp] = lp;
                split2(acc[mt][nt][2], acc[mt][nt][3], hp, lp);
                Ch[(size_t)(r + 8) * KPR + kp] = hp;
                Cl[(size_t)(r + 8) * KPR + kp] = lp;
            } else {
                *(float2*)&C[(size_t)r * N + c] =
                    make_float2(acc[mt][nt][0], acc[mt][nt][1]);
                *(float2*)&C[(size_t)(r + 8) * N + c] =
                    make_float2(acc[mt][nt][2], acc[mt][nt][3]);
            }
        }
    }
}

// ---------------------------------------------------------------------------
// Tensor-core windowed flash attention (unchanged from R9 best):
// split-bf16 ldmatrix fragments, pre-split inputs, fixed-max softmax,
// 256 threads, 6 chunks of 96 keys, 2 CTAs/SM.
// ---------------------------------------------------------------------------
constexpr int AQT = 64;
constexpr int AKT = 96;
constexpr int NCHUNK = 6;
constexpr int QSTR2 = 36;
constexpr int KSTR2 = 36;
constexpr int VSTR2 = 52;
constexpr int PSTR2 = 52;
constexpr int ATHREADS = 256;
constexpr float FIXM = 12.0f;

constexpr int OFF_QH = 0;
constexpr int OFF_QL = OFF_QH + AQT * QSTR2;
constexpr int OFF_KH = OFF_QL + AQT * QSTR2;
constexpr int OFF_KL = OFF_KH + AKT * KSTR2;
constexpr int OFF_VH = OFF_KL + AKT * KSTR2;
constexpr int OFF_VL = OFF_VH + 64 * VSTR2;
constexpr int OFF_PH = OFF_VL + 64 * VSTR2;
constexpr int OFF_PL = OFF_PH + AQT * PSTR2;
constexpr int OFF_RED = OFF_PL + AQT * PSTR2;
constexpr int ATTN_SMEM_WORDS = OFF_RED + 128;
constexpr int ATTN_SMEM_BYTES = ATTN_SMEM_WORDS * 4;  // 99840

__global__ __launch_bounds__(ATHREADS, 2) void attn_tc_kernel()
{
    extern __shared__ uint32_t sm[];
    uint32_t* sQh = sm + OFF_QH;
    uint32_t* sQl = sm + OFF_QL;
    uint32_t* sKh = sm + OFF_KH;
    uint32_t* sKl = sm + OFF_KL;
    uint32_t* sVh = sm + OFF_VH;
    uint32_t* sVl = sm + OFF_VL;
    uint32_t* sPh = sm + OFF_PH;
    uint32_t* sPl = sm + OFF_PL;
    float* red = (float*)(sm + OFF_RED);

    const int tid  = threadIdx.x;
    const int lane = tid & 31;
    const int wid  = tid >> 5;
    const int gr = lane >> 2;
    const int qc = lane & 3;
    const int wm = wid >> 1;
    const int wn = wid & 1;
    const int m0 = wm * 16;

    const int t0 = blockIdx.x * AQT;
    const int h  = blockIdx.y;
    const int b  = blockIdx.z;
    const float slope = exp2f(-(float)(h + 1));

    const uint32_t* Qh_p = g_qh + ((size_t)(b * S_LEN + t0)) * KPR + h * 32;
    const uint32_t* Ql_p = g_ql + ((size_t)(b * S_LEN + t0)) * KPR + h * 32;
    const uint32_t* Kh_p = g_kh + ((size_t)b * S_LEN) * KPR + h * 32;
    const uint32_t* Kl_p = g_kl + ((size_t)b * S_LEN) * KPR + h * 32;
    const uint32_t* Vh_p = g_vh + ((size_t)b * S_LEN) * KPR + h * 32;
    const uint32_t* Vl_p = g_vl + ((size_t)b * S_LEN) * KPR + h * 32;
    float* Ob = g_att + (size_t)b * S_LEN * EMB + h * DH;

    const int lrow8  = (lane & 7);
    const int lmsel  = (lane >> 3) & 1;
    const int lhsel  = (lane >> 4) & 1;

    const uint32_t qh_base = smem_u32(sQh) +
        (((m0 + lrow8 + lmsel * 8) * QSTR2) + lhsel * 4) * 4;
    const uint32_t ql_base = qh_base + (OFF_QL - OFF_QH) * 4;
    const uint32_t ph_base = smem_u32(sPh) +
        (((m0 + lrow8 + lmsel * 8) * PSTR2) + lhsel * 4) * 4;
    const uint32_t pl_base = ph_base + (OFF_PL - OFF_PH) * 4;
    const int nbase = wn * 48;
    const uint32_t kh_base = smem_u32(sKh) +
        (((nbase + lrow8 + lhsel * 8) * KSTR2) + lmsel * 4) * 4;
    const uint32_t kl_base = kh_base + (OFF_KL - OFF_KH) * 4;
    const int nb2 = wn * 32;
    const uint32_t vh_base = smem_u32(sVh) +
        (((nb2 + lrow8 + lhsel * 8) * VSTR2) + lmsel * 4) * 4;
    const uint32_t vl_base = vh_base + (OFF_VL - OFF_VH) * 4;

    for (int idx = tid; idx < 512; idx += ATHREADS) {
        int q = idx >> 3;
        int j = idx & 7;
        uint4 vh = *(const uint4*)&Qh_p[(size_t)q * KPR + j * 4];
        uint4 vl = *(const uint4*)&Ql_p[(size_t)q * KPR + j * 4];
        *(uint4*)&sQh[q * QSTR2 + j * 4] = vh;
        *(uint4*)&sQl[q * QSTR2 + j * 4] = vl;
    }

    float o[4][4] = {};
    float sum0 = 0.f, sum1 = 0.f;

    const int base = t0 - HALF;

    #pragma unroll 1
    for (int c = 0; c < NCHUNK; c++) {
        const int cs = base + c * AKT;
        if (cs + AKT <= 0 || cs >= S_LEN) continue;

        for (int idx = tid; idx < 768; idx += ATHREADS) {
            int key = idx >> 3;
            int j = idx & 7;
            int T = cs + key;
            uint4 vh = make_uint4(0, 0, 0, 0);
            uint4 vl = make_uint4(0, 0, 0, 0);
            if (T >= 0 && T < S_LEN) {
                vh = *(const uint4*)&Kh_p[(size_t)T * KPR + j * 4];
                vl = *(const uint4*)&Kl_p[(size_t)T * KPR + j * 4];
            }
            *(uint4*)&sKh[key * KSTR2 + j * 4] = vh;
            *(uint4*)&sKl[key * KSTR2 + j * 4] = vl;
        }
        for (int idx = tid; idx < 384; idx += ATHREADS) {
            int kp = idx >> 3;
            int j = idx & 7;
            int T0 = cs + 2 * kp, T1 = T0 + 1;
            uint4 ah = make_uint4(0, 0, 0, 0), al = make_uint4(0, 0, 0, 0);
            uint4 bh = make_uint4(0, 0, 0, 0), bl = make_uint4(0, 0, 0, 0);
            if (T0 >= 0 && T0 < S_LEN) {
                ah = *(const uint4*)&Vh_p[(size_t)T0 * KPR + j * 4];
                al = *(const uint4*)&Vl_p[(size_t)T0 * KPR + j * 4];
            }
            if (T1 >= 0 && T1 < S_LEN) {
                bh = *(const uint4*)&Vh_p[(size_t)T1 * KPR + j * 4];
                bl = *(const uint4*)&Vl_p[(size_t)T1 * KPR + j * 4];
            }
            int d0 = 8 * j;
            sVh[(d0 + 0) * VSTR2 + kp] = prmt(ah.x, bh.x, 0x5410);
            sVh[(d0 + 1) * VSTR2 + kp] = prmt(ah.x, bh.x, 0x7632);
            sVh[(d0 + 2) * VSTR2 + kp] = prmt(ah.y, bh.y, 0x5410);
            sVh[(d0 + 3) * VSTR2 + kp] = prmt(ah.y, bh.y, 0x7632);
            sVh[(d0 + 4) * VSTR2 + kp] = prmt(ah.z, bh.z, 0x5410);
            sVh[(d0 + 5) * VSTR2 + kp] = prmt(ah.z, bh.z, 0x7632);
            sVh[(d0 + 6) * VSTR2 + kp] = prmt(ah.w, bh.w, 0x5410);
            sVh[(d0 + 7) * VSTR2 + kp] = prmt(ah.w, bh.w, 0x7632);
            sVl[(d0 + 0) * VSTR2 + kp] = prmt(al.x, bl.x, 0x5410);
            sVl[(d0 + 1) * VSTR2 + kp] = prmt(al.x, bl.x, 0x7632);
            sVl[(d0 + 2) * VSTR2 + kp] = prmt(al.y, bl.y, 0x5410);
            sVl[(d0 + 3) * VSTR2 + kp] = prmt(al.y, bl.y, 0x7632);
            sVl[(d0 + 4) * VSTR2 + kp] = prmt(al.z, bl.z, 0x5410);
            sVl[(d0 + 5) * VSTR2 + kp] = prmt(al.z, bl.z, 0x7632);
            sVl[(d0 + 6) * VSTR2 + kp] = prmt(al.w, bl.w, 0x5410);
            sVl[(d0 + 7) * VSTR2 + kp] = prmt(al.w, bl.w, 0x7632);
        }
        __syncthreads();

        float s[6][4];
        #pragma unroll
        for (int nt = 0; nt < 6; nt++)
            #pragma unroll
            for (int i = 0; i < 4; i++) s[nt][i] = 0.f;

        #pragma unroll
        for (int ks = 0; ks < 4; ks++) {
            uint32_t ah[4], al[4];
            ldsm_x4(ah, qh_base + ks * 32);
            ldsm_x4(al, ql_base + ks * 32);
            #pragma unroll
            for (int ntp = 0; ntp < 3; ntp++) {
                uint32_t bh[4], bl[4];
                ldsm_x4(bh, kh_base + ks * 32 + ntp * (16 * KSTR2 * 4));
                ldsm_x4(bl, kl_base + ks * 32 + ntp * (16 * KSTR2 * 4));
                mma_bf16(s[2 * ntp],     ah, bh);
                mma_bf16(s[2 * ntp],     ah, bl);
                mma_bf16(s[2 * ntp],     al, bh);
                mma_bf16(s[2 * ntp + 1], ah, bh + 2);
                mma_bf16(s[2 * ntp + 1], ah, bl + 2);
                mma_bf16(s[2 * ntp + 1], al, bh + 2);
            }
        }

        const int trow0 = t0 + m0 + gr;
        const int trow1 = trow0 + 8;
        #pragma unroll
        for (int nt = 0; nt < 6; nt++) {
            int T0 = cs + nbase + nt * 8 + 2 * qc;
            int T1 = T0 + 1;
            bool in0 = (T0 >= 0) && (T0 < S_LEN);
            bool in1 = (T1 >= 0) && (T1 < S_LEN);
            int a00 = abs(trow0 - T0), a01 = abs(trow0 - T1);
            int a10 = abs(trow1 - T0), a11 = abs(trow1 - T1);
            float p00 = (in0 && a00 <= HALF)
                ? __expf(fmaf(s[nt][0], 0.125f, fmaf(-slope, (float)a00, -FIXM))) : 0.f;
            float p01 = (in1 && a01 <= HALF)
                ? __expf(fmaf(s[nt][1], 0.125f, fmaf(-slope, (float)a01, -FIXM))) : 0.f;
            float p10 = (in0 && a10 <= HALF)
                ? __expf(fmaf(s[nt][2], 0.125f, fmaf(-slope, (float)a10, -FIXM))) : 0.f;
            float p11 = (in1 && a11 <= HALF)
                ? __expf(fmaf(s[nt][3], 0.125f, fmaf(-slope, (float)a11, -FIXM))) : 0.f;
            sum0 += p00 + p01;
            sum1 += p10 + p11;
            int kp = wn * 24 + nt * 4 + qc;
            uint32_t hp, lp;
            split2(p00, p01, hp, lp);
            sPh[(m0 + gr) * PSTR2 + kp] = hp;
            sPl[(m0 + gr) * PSTR2 + kp] = lp;
            split2(p10, p11, hp, lp);
            sPh[(m0 + gr + 8) * PSTR2 + kp] = hp;
            sPl[(m0 + gr + 8) * PSTR2 + kp] = lp;
        }
        __syncthreads();

        #pragma unroll
        for (int ks = 0; ks < 6; ks++) {
            uint32_t ah[4], al[4];
            ldsm_x4(ah, ph_base + ks * 32);
            ldsm_x4(al, pl_base + ks * 32);
            #pragma unroll
            for (int ntp = 0; ntp < 2; ntp++) {
                uint32_t bh[4], bl[4];
                ldsm_x4(bh, vh_base + ks * 32 + ntp * (16 * VSTR2 * 4));
                ldsm_x4(bl, vl_base + ks * 32 + ntp * (16 * VSTR2 * 4));
                mma_bf16(o[2 * ntp],     ah, bh);
                mma_bf16(o[2 * ntp],     ah, bl);
                mma_bf16(o[2 * ntp],     al, bh);
                mma_bf16(o[2 * ntp + 1], ah, bh + 2);
                mma_bf16(o[2 * ntp + 1], ah, bl + 2);
                mma_bf16(o[2 * ntp + 1], al, bh + 2);
            }
        }
        __syncthreads();
    }

    sum0 += __shfl_xor_sync(0xffffffffu, sum0, 1);
    sum0 += __shfl_xor_sync(0xffffffffu, sum0, 2);
    sum1 += __shfl_xor_sync(0xffffffffu, sum1, 1);
    sum1 += __shfl_xor_sync(0xffffffffu, sum1, 2);
    if (qc == 0) {
        red[(m0 + gr) * 2 + wn] = sum0;
        red[(m0 + gr + 8) * 2 + wn] = sum1;
    }
    __syncthreads();

    const int trow0 = t0 + m0 + gr;
    const float inv0 = 1.0f / (red[(m0 + gr) * 2] + red[(m0 + gr) * 2 + 1]);
    const float inv1 = 1.0f / (red[(m0 + gr + 8) * 2] + red[(m0 + gr + 8) * 2 + 1]);
    #pragma unroll
    for (int nt = 0; nt < 4; nt++) {
        int d = nb2 + nt * 8 + 2 * qc;
        *(float2*)&Ob[(size_t)trow0 * EMB + d] =
            make_float2(o[nt][0] * inv0, o[nt][1] * inv0);
        *(float2*)&Ob[(size_t)(trow0 + 8) * EMB + d] =
            make_float2(o[nt][2] * inv1, o[nt][3] * inv1);
    }
}

// ---------------------------------------------------------------------------
extern "C" void kernel_launch(void* const* d_in, const int* in_sizes, int n_in,
                              void* d_out, int out_size)
{
    (void)in_sizes; (void)n_in; (void)out_size;
    const float* inputs_q  = (const float*)d_in[0];
    const float* inputs_kv = (const float*)d_in[1];
    const float* w_q = (const float*)d_in[2];
    const float* w_k = (const float*)d_in[3];
    const float* w_v = (const float*)d_in[4];
    const float* w_o = (const float*)d_in[5];
    float* out = (float*)d_out;

    uint32_t *qh, *ql, *kh, *kl, *vh, *vl;
    float* ab;
    cudaGetSymbolAddress((void**)&qh, g_qh);
    cudaGetSymbolAddress((void**)&ql, g_ql);
    cudaGetSymbolAddress((void**)&kh, g_kh);
    cudaGetSymbolAddress((void**)&kl, g_kl);
    cudaGetSymbolAddress((void**)&vh, g_vh);
    cudaGetSymbolAddress((void**)&vl, g_vl);
    cudaGetSymbolAddress((void**)&ab, g_att);

    cudaFuncSetAttribute(gemm_bf16_kernel<true>,
                         cudaFuncAttributeMaxDynamicSharedMemorySize,
                         GEMM_SMEM_BYTES);
    cudaFuncSetAttribute(gemm_bf16_kernel<false>,
                         cudaFuncAttributeMaxDynamicSharedMemorySize,
                         GEMM_SMEM_BYTES);
    cudaFuncSetAttribute(attn_tc_kernel,
                         cudaFuncAttributeMaxDynamicSharedMemorySize,
                         ATTN_SMEM_BYTES);

    dim3 gGemm(EMB / GBN, ROWS / GBM);   // (8, 64) = 512 CTAs
    gemm_bf16_kernel<true><<<gGemm, 256, GEMM_SMEM_BYTES>>>(
        inputs_q,  w_q, nullptr, qh, ql, ROWS, EMB, EMB);
    gemm_bf16_kernel<true><<<gGemm, 256, GEMM_SMEM_BYTES>>>(
        inputs_kv, w_k, nullptr, kh, kl, ROWS, EMB, EMB);
    gemm_bf16_kernel<true><<<gGemm, 256, GEMM_SMEM_BYTES>>>(
        inputs_kv, w_v, nullptr, vh, vl, ROWS, EMB, EMB);

    dim3 gAttn(S_LEN / AQT, NH, BATCH);  // (64, 8, 2)
    attn_tc_kernel<<<gAttn, ATHREADS, ATTN_SMEM_BYTES>>>();

    gemm_bf16_kernel<false><<<gGemm, 256, GEMM_SMEM_BYTES>>>(
        ab, w_o, out, nullptr, nullptr, ROWS, EMB, EMB);
}

// round 13
// speedup vs baseline: 1.0014x; 1.0014x over previous
#include <cuda_runtime.h>
#include <math.h>
#include <stdint.h>

// Problem constants
constexpr int S_LEN = 4096;
constexpr int BATCH = 2;
constexpr int EMB   = 512;   // E and also H*D
constexpr int NH    = 8;
constexpr int DH    = 64;
constexpr int HALF  = 256;   // sliding window half-width
constexpr int ROWS  = BATCH * S_LEN;  // 8192
constexpr int KPR   = EMB / 2;        // 256 kpairs per row

// Scratch (allocation-free rule: __device__ globals)
// Pre-split planes of GEMM operands (bf16x2 hi/lo):
__device__ uint32_t g_iqh[(size_t)ROWS * KPR];   // inputs_q pairs
__device__ uint32_t g_iql[(size_t)ROWS * KPR];
__device__ uint32_t g_ikh[(size_t)ROWS * KPR];   // inputs_kv pairs
__device__ uint32_t g_ikl[(size_t)ROWS * KPR];
__device__ uint32_t g_wqh[(size_t)KPR * EMB];    // weights, row-pairs
__device__ uint32_t g_wql[(size_t)KPR * EMB];
__device__ uint32_t g_wkh[(size_t)KPR * EMB];
__device__ uint32_t g_wkl[(size_t)KPR * EMB];
__device__ uint32_t g_wvh[(size_t)KPR * EMB];
__device__ uint32_t g_wvl[(size_t)KPR * EMB];
__device__ uint32_t g_woh[(size_t)KPR * EMB];
__device__ uint32_t g_wol[(size_t)KPR * EMB];
// Projected q/k/v planes (written by GEMM epilogue, read by attention):
__device__ uint32_t g_qh[(size_t)ROWS * KPR];
__device__ uint32_t g_ql[(size_t)ROWS * KPR];
__device__ uint32_t g_kh[(size_t)ROWS * KPR];
__device__ uint32_t g_kl[(size_t)ROWS * KPR];
__device__ uint32_t g_vh[(size_t)ROWS * KPR];
__device__ uint32_t g_vl[(size_t)ROWS * KPR];
// Attention output planes (A of the output projection):
__device__ uint32_t g_ath[(size_t)ROWS * KPR];
__device__ uint32_t g_atl[(size_t)ROWS * KPR];

// ---------------------------------------------------------------------------
// helpers
// ---------------------------------------------------------------------------
__device__ __forceinline__ void split2(float x0, float x1,
                                       uint32_t& hp, uint32_t& lp) {
    asm("cvt.rn.bf16x2.f32 %0, %1, %2;" : "=r"(hp) : "f"(x1), "f"(x0));
    float h0 = __uint_as_float(hp << 16);
    float h1 = __uint_as_float(hp & 0xffff0000u);
    float r0 = x0 - h0;
    float r1 = x1 - h1;
    asm("cvt.rn.bf16x2.f32 %0, %1, %2;" : "=r"(lp) : "f"(r1), "f"(r0));
}

__device__ __forceinline__ void mma_bf16(float d[4], const uint32_t a[4],
                                         const uint32_t b[2]) {
    asm volatile(
        "mma.sync.aligned.m16n8k16.row.col.f32.bf16.bf16.f32 "
        "{%0,%1,%2,%3}, {%4,%5,%6,%7}, {%8,%9}, {%0,%1,%2,%3};\n"
        : "+f"(d[0]), "+f"(d[1]), "+f"(d[2]), "+f"(d[3])
        : "r"(a[0]), "r"(a[1]), "r"(a[2]), "r"(a[3]), "r"(b[0]), "r"(b[1]));
}

__device__ __forceinline__ void ldsm_x4(uint32_t r[4], uint32_t addr) {
    asm volatile(
        "ldmatrix.sync.aligned.m8n8.x4.shared.b16 {%0,%1,%2,%3}, [%4];"
        : "=r"(r[0]), "=r"(r[1]), "=r"(r[2]), "=r"(r[3]) : "r"(addr));
}

__device__ __forceinline__ uint32_t smem_u32(const void* p) {
    return (uint32_t)__cvta_generic_to_shared(p);
}

__device__ __forceinline__ uint32_t prmt(uint32_t a, uint32_t b, uint32_t s) {
    uint32_t d;
    asm("prmt.b32 %0, %1, %2, %3;" : "=r"(d) : "r"(a), "r"(b), "r"(s));
    return d;
}

// ---------------------------------------------------------------------------
// Pre-split kernels
// ---------------------------------------------------------------------------
// Pairs along the contiguous dimension (A-type operands).
__global__ __launch_bounds__(256) void presplit_pairs(
    const float4* __restrict__ src, uint2* __restrict__ h,
    uint2* __restrict__ l, int n4)
{
    int i = blockIdx.x * blockDim.x + threadIdx.x;
    if (i < n4) {
        float4 v = src[i];
        uint32_t h0, l0, h1, l1;
        split2(v.x, v.y, h0, l0);
        split2(v.z, v.w, h1, l1);
        h[i] = make_uint2(h0, h1);
        l[i] = make_uint2(l0, l1);
    }
}

// Row-pairs for B-type operands (weights [512][512] -> planes [256][512]).
__global__ __launch_bounds__(256) void presplit_wB(
    const float* __restrict__ B, uint32_t* __restrict__ h,
    uint32_t* __restrict__ l)
{
    int i = blockIdx.x * blockDim.x + threadIdx.x;   // 0..32767
    int kp = i >> 7;            // 0..255
    int c4 = (i & 127) * 4;     // 0..508
    float4 a = *(const float4*)&B[(size_t)(2 * kp) * EMB + c4];
    float4 b = *(const float4*)&B[(size_t)(2 * kp + 1) * EMB + c4];
    uint32_t h0, l0, h1, l1, h2, l2, h3, l3;
    split2(a.x, b.x, h0, l0);
    split2(a.y, b.y, h1, l1);
    split2(a.z, b.z, h2, l2);
    split2(a.w, b.w, h3, l3);
    *(uint4*)&h[(size_t)kp * EMB + c4] = make_uint4(h0, h1, h2, h3);
    *(uint4*)&l[(size_t)kp * EMB + c4] = make_uint4(l0, l1, l2, l3);
}

// ---------------------------------------------------------------------------
// Split-bf16 tensor-core GEMM on PRE-SPLIT planes (mainloop = pure copies).
// C[M=8192, N=512] = A[M, K=512] @ B[K, N].
// CTA tile 128x128 (R9-validated shape), BK=32 (16 kpairs), 256 threads,
// 8 warps (2x4 -> 64x32 warp tiles), double-buffered + register prefetch.
// A smem [m][kp] stride 20; B smem [kp][n] stride 136 (both conflict-free).
// SPLIT_OUT=true: epilogue writes bf16x2 hi/lo planes; else fp32.
// ---------------------------------------------------------------------------
constexpr int GBM = 128, GBN = 128;
constexpr int TKP = 16;                 // kpairs per k-tile (BK=32)
constexpr int ASTR = 20;
constexpr int BSTR = 136;
constexpr int A_STAGE = GBM * ASTR;     // 2560
constexpr int B_STAGE = TKP * BSTR;     // 2176
constexpr int GEMM_SMEM_BYTES = (4 * A_STAGE + 4 * B_STAGE) * 4;  // 75776

template <bool SPLIT_OUT>
__global__ __launch_bounds__(256, 1) void gemm_ps_kernel(
    const uint32_t* __restrict__ Ah_g, const uint32_t* __restrict__ Al_g,
    const uint32_t* __restrict__ Bh_g, const uint32_t* __restrict__ Bl_g,
    float* __restrict__ C, uint32_t* __restrict__ Ch, uint32_t* __restrict__ Cl)
{
    extern __shared__ uint32_t sm[];
    uint32_t* sAh = sm;
    uint32_t* sAl = sAh + 2 * A_STAGE;
    uint32_t* sBh = sAl + 2 * A_STAGE;
    uint32_t* sBl = sBh + 2 * B_STAGE;

    const int tid  = threadIdx.x;
    const int lane = tid & 31;
    const int wid  = tid >> 5;
    const int m_base = (wid >> 2) * 64;
    const int n_base = (wid & 3) * 32;
    const int row0 = blockIdx.y * GBM;
    const int col0 = blockIdx.x * GBN;

    // A: rows arow, arow+64; 4 kpairs at akp.  B: kp rows brow, brow+8; 4 n at bcol.
    const int arow = tid >> 2;
    const int akp  = (tid & 3) * 4;
    const int brow = tid >> 5;
    const int bcol = (tid & 31) * 4;

    const uint32_t* pAh0 = Ah_g + (size_t)(row0 + arow) * KPR + akp;
    const uint32_t* pAl0 = Al_g + (size_t)(row0 + arow) * KPR + akp;
    const uint32_t* pAh1 = pAh0 + (size_t)64 * KPR;
    const uint32_t* pAl1 = pAl0 + (size_t)64 * KPR;
    const uint32_t* pBh0 = Bh_g + (size_t)brow * EMB + col0 + bcol;
    const uint32_t* pBl0 = Bl_g + (size_t)brow * EMB + col0 + bcol;
    const uint32_t* pBh1 = pBh0 + (size_t)8 * EMB;
    const uint32_t* pBl1 = pBl0 + (size_t)8 * EMB;

    const int NT = KPR / TKP;   // 16

    float acc[4][4][4] = {};
    uint4 ah0, al0, ah1, al1, bh0, bl0, bh1, bl1;

    ah0 = *(const uint4*)(pAh0);
    al0 = *(const uint4*)(pAl0);
    ah1 = *(const uint4*)(pAh1);
    al1 = *(const uint4*)(pAl1);
    bh0 = *(const uint4*)(pBh0);
    bl0 = *(const uint4*)(pBl0);
    bh1 = *(const uint4*)(pBh1);
    bl1 = *(const uint4*)(pBl1);

    #define STAGE_STORE(buf)                                                  \
        {                                                                     \
            uint32_t* dAh = sAh + (buf) * A_STAGE;                            \
            uint32_t* dAl = sAl + (buf) * A_STAGE;                            \
            uint32_t* dBh = sBh + (buf) * B_STAGE;                            \
            uint32_t* dBl = sBl + (buf) * B_STAGE;                            \
            *(uint4*)&dAh[arow * ASTR + akp] = ah0;                           \
            *(uint4*)&dAl[arow * ASTR + akp] = al0;                           \
            *(uint4*)&dAh[(arow + 64) * ASTR + akp] = ah1;                    \
            *(uint4*)&dAl[(arow + 64) * ASTR + akp] = al1;                    \
            *(uint4*)&dBh[brow * BSTR + bcol] = bh0;                          \
            *(uint4*)&dBl[brow * BSTR + bcol] = bl0;                          \
            *(uint4*)&dBh[(brow + 8) * BSTR + bcol] = bh1;                    \
            *(uint4*)&dBl[(brow + 8) * BSTR + bcol] = bl1;                    \
        }

    STAGE_STORE(0);
    __syncthreads();

    const int gr = lane >> 2;
    const int qc = lane & 3;

    for (int kt = 0; kt < NT; kt++) {
        if (kt + 1 < NT) {
            int ko = (kt + 1) * TKP;                 // kpair offset (A)
            ah0 = *(const uint4*)(pAh0 + ko);
            al0 = *(const uint4*)(pAl0 + ko);
            ah1 = *(const uint4*)(pAh1 + ko);
            al1 = *(const uint4*)(pAl1 + ko);
            size_t bo = (size_t)(kt + 1) * TKP * EMB;  // kp-row offset (B)
            bh0 = *(const uint4*)(pBh0 + bo);
            bl0 = *(const uint4*)(pBl0 + bo);
            bh1 = *(const uint4*)(pBh1 + bo);
            bl1 = *(const uint4*)(pBl1 + bo);
        }

        const uint32_t* Ah = sAh + (kt & 1) * A_STAGE;
        const uint32_t* Al = sAl + (kt & 1) * A_STAGE;
        const uint32_t* Bh = sBh + (kt & 1) * B_STAGE;
        const uint32_t* Bl = sBl + (kt & 1) * B_STAGE;

        #pragma unroll
        for (int ks = 0; ks < 2; ks++) {
            const int kp0 = ks * 8 + qc;
            uint32_t ah[4][4], al[4][4], bh[4][2], bl[4][2];
            #pragma unroll
            for (int mt = 0; mt < 4; mt++) {
                const int m = m_base + mt * 16 + gr;
                ah[mt][0] = Ah[m * ASTR + kp0];
                ah[mt][1] = Ah[(m + 8) * ASTR + kp0];
                ah[mt][2] = Ah[m * ASTR + kp0 + 4];
                ah[mt][3] = Ah[(m + 8) * ASTR + kp0 + 4];
                al[mt][0] = Al[m * ASTR + kp0];
                al[mt][1] = Al[(m + 8) * ASTR + kp0];
                al[mt][2] = Al[m * ASTR + kp0 + 4];
                al[mt][3] = Al[(m + 8) * ASTR + kp0 + 4];
            }
            #pragma unroll
            for (int nt = 0; nt < 4; nt++) {
                const int n = n_base + nt * 8 + gr;
                bh[nt][0] = Bh[kp0 * BSTR + n];
                bh[nt][1] = Bh[(kp0 + 4) * BSTR + n];
                bl[nt][0] = Bl[kp0 * BSTR + n];
                bl[nt][1] = Bl[(kp0 + 4) * BSTR + n];
            }
            #pragma unroll
            for (int mt = 0; mt < 4; mt++)
                #pragma unroll
                for (int nt = 0; nt < 4; nt++) {
                    mma_bf16(acc[mt][nt], ah[mt], bh[nt]);
                    mma_bf16(acc[mt][nt], ah[mt], bl[nt]);
                    mma_bf16(acc[mt][nt], al[mt], bh[nt]);
                }
        }

        if (kt + 1 < NT) {
            STAGE_STORE((kt + 1) & 1);
        }
        __syncthreads();
    }
    #undef STAGE_STORE

    #pragma unroll
    for (int mt = 0; mt < 4; mt++) {
        #pragma unroll
        for (int nt = 0; nt < 4; nt++) {
            int r = row0 + m_base + mt * 16 + gr;
            int c = col0 + n_base + nt * 8 + 2 * qc;
            if constexpr (SPLIT_OUT) {
                int kp = c >> 1;
                uint32_t hp, lp;
                split2(acc[mt][nt][0], acc[mt][nt][1], hp, lp);
                Ch[(size_t)r * KPR + kp] = hp;
                Cl[(size_t)r * KPR + kp] = lp;
                split2(acc[mt][nt][2], acc[mt][nt][3], hp, lp);
                Ch[(size_t)(r + 8) * KPR + kp] = hp;
                Cl[(size_t)(r + 8) * KPR + kp] = lp;
            } else {
                *(float2*)&C[(size_t)r * EMB + c] =
                    make_float2(acc[mt][nt][0], acc[mt][nt][1]);
                *(float2*)&C[(size_t)(r + 8) * EMB + c] =
                    make_float2(acc[mt][nt][2], acc[mt][nt][3]);
            }
        }
    }
}

// ---------------------------------------------------------------------------
// Tensor-core windowed flash attention (R9-validated): split-bf16 ldmatrix
// fragments, pre-split inputs, fixed-max softmax, 256 threads, 6 chunks of
// 96 keys, 2 CTAs/SM. Epilogue now writes PRE-SPLIT output planes.
// ---------------------------------------------------------------------------
constexpr int AQT = 64;
constexpr int AKT = 96;
constexpr int NCHUNK = 6;
constexpr int QSTR2 = 36;
constexpr int KSTR2 = 36;
constexpr int VSTR2 = 52;
constexpr int PSTR2 = 52;
constexpr int ATHREADS = 256;
constexpr float FIXM = 12.0f;

constexpr int OFF_QH = 0;
constexpr int OFF_QL = OFF_QH + AQT * QSTR2;
constexpr int OFF_KH = OFF_QL + AQT * QSTR2;
constexpr int OFF_KL = OFF_KH + AKT * KSTR2;
constexpr int OFF_VH = OFF_KL + AKT * KSTR2;
constexpr int OFF_VL = OFF_VH + 64 * VSTR2;
constexpr int OFF_PH = OFF_VL + 64 * VSTR2;
constexpr int OFF_PL = OFF_PH + AQT * PSTR2;
constexpr int OFF_RED = OFF_PL + AQT * PSTR2;
constexpr int ATTN_SMEM_WORDS = OFF_RED + 128;
constexpr int ATTN_SMEM_BYTES = ATTN_SMEM_WORDS * 4;  // 99840

__global__ __launch_bounds__(ATHREADS, 2) void attn_tc_kernel()
{
    extern __shared__ uint32_t sm[];
    uint32_t* sQh = sm + OFF_QH;
    uint32_t* sQl = sm + OFF_QL;
    uint32_t* sKh = sm + OFF_KH;
    uint32_t* sKl = sm + OFF_KL;
    uint32_t* sVh = sm + OFF_VH;
    uint32_t* sVl = sm + OFF_VL;
    uint32_t* sPh = sm + OFF_PH;
    uint32_t* sPl = sm + OFF_PL;
    float* red = (float*)(sm + OFF_RED);

    const int tid  = threadIdx.x;
    const int lane = tid & 31;
    const int wid  = tid >> 5;
    const int gr = lane >> 2;
    const int qc = lane & 3;
    const int wm = wid >> 1;
    const int wn = wid & 1;
    const int m0 = wm * 16;

    const int t0 = blockIdx.x * AQT;
    const int h  = blockIdx.y;
    const int b  = blockIdx.z;
    const float slope = exp2f(-(float)(h + 1));

    const uint32_t* Qh_p = g_qh + ((size_t)(b * S_LEN + t0)) * KPR + h * 32;
    const uint32_t* Ql_p = g_ql + ((size_t)(b * S_LEN + t0)) * KPR + h * 32;
    const uint32_t* Kh_p = g_kh + ((size_t)b * S_LEN) * KPR + h * 32;
    const uint32_t* Kl_p = g_kl + ((size_t)b * S_LEN) * KPR + h * 32;
    const uint32_t* Vh_p = g_vh + ((size_t)b * S_LEN) * KPR + h * 32;
    const uint32_t* Vl_p = g_vl + ((size_t)b * S_LEN) * KPR + h * 32;

    const int lrow8  = (lane & 7);
    const int lmsel  = (lane >> 3) & 1;
    const int lhsel  = (lane >> 4) & 1;

    const uint32_t qh_base = smem_u32(sQh) +
        (((m0 + lrow8 + lmsel * 8) * QSTR2) + lhsel * 4) * 4;
    const uint32_t ql_base = qh_base + (OFF_QL - OFF_QH) * 4;
    const uint32_t ph_base = smem_u32(sPh) +
        (((m0 + lrow8 + lmsel * 8) * PSTR2) + lhsel * 4) * 4;
    const uint32_t pl_base = ph_base + (OFF_PL - OFF_PH) * 4;
    const int nbase = wn * 48;
    const uint32_t kh_base = smem_u32(sKh) +
        (((nbase + lrow8 + lhsel * 8) * KSTR2) + lmsel * 4) * 4;
    const uint32_t kl_base = kh_base + (OFF_KL - OFF_KH) * 4;
    const int nb2 = wn * 32;
    const uint32_t vh_base = smem_u32(sVh) +
        (((nb2 + lrow8 + lhsel * 8) * VSTR2) + lmsel * 4) * 4;
    const uint32_t vl_base = vh_base + (OFF_VL - OFF_VH) * 4;

    for (int idx = tid; idx < 512; idx += ATHREADS) {
        int q = idx >> 3;
        int j = idx & 7;
        uint4 vh = *(const uint4*)&Qh_p[(size_t)q * KPR + j * 4];
        uint4 vl = *(const uint4*)&Ql_p[(size_t)q * KPR + j * 4];
        *(uint4*)&sQh[q * QSTR2 + j * 4] = vh;
        *(uint4*)&sQl[q * QSTR2 + j * 4] = vl;
    }

    float o[4][4] = {};
    float sum0 = 0.f, sum1 = 0.f;

    const int base = t0 - HALF;

    #pragma unroll 1
    for (int c = 0; c < NCHUNK; c++) {
        const int cs = base + c * AKT;
        if (cs + AKT <= 0 || cs >= S_LEN) continue;

        for (int idx = tid; idx < 768; idx += ATHREADS) {
            int key = idx >> 3;
            int j = idx & 7;
            int T = cs + key;
            uint4 vh = make_uint4(0, 0, 0, 0);
            uint4 vl = make_uint4(0, 0, 0, 0);
            if (T >= 0 && T < S_LEN) {
                vh = *(const uint4*)&Kh_p[(size_t)T * KPR + j * 4];
                vl = *(const uint4*)&Kl_p[(size_t)T * KPR + j * 4];
            }
            *(uint4*)&sKh[key * KSTR2 + j * 4] = vh;
            *(uint4*)&sKl[key * KSTR2 + j * 4] = vl;
        }
        for (int idx = tid; idx < 384; idx += ATHREADS) {
            int kp = idx >> 3;
            int j = idx & 7;
            int T0 = cs + 2 * kp, T1 = T0 + 1;
            uint4 ah = make_uint4(0, 0, 0, 0), al = make_uint4(0, 0, 0, 0);
            uint4 bh = make_uint4(0, 0, 0, 0), bl = make_uint4(0, 0, 0, 0);
            if (T0 >= 0 && T0 < S_LEN) {
                ah = *(const uint4*)&Vh_p[(size_t)T0 * KPR + j * 4];
                al = *(const uint4*)&Vl_p[(size_t)T0 * KPR + j * 4];
            }
            if (T1 >= 0 && T1 < S_LEN) {
                bh = *(const uint4*)&Vh_p[(size_t)T1 * KPR + j * 4];
                bl = *(const uint4*)&Vl_p[(size_t)T1 * KPR + j * 4];
            }
            int d0 = 8 * j;
            sVh[(d0 + 0) * VSTR2 + kp] = prmt(ah.x, bh.x, 0x5410);
            sVh[(d0 + 1) * VSTR2 + kp] = prmt(ah.x, bh.x, 0x7632);
            sVh[(d0 + 2) * VSTR2 + kp] = prmt(ah.y, bh.y, 0x5410);
            sVh[(d0 + 3) * VSTR2 + kp] = prmt(ah.y, bh.y, 0x7632);
            sVh[(d0 + 4) * VSTR2 + kp] = prmt(ah.z, bh.z, 0x5410);
            sVh[(d0 + 5) * VSTR2 + kp] = prmt(ah.z, bh.z, 0x7632);
            sVh[(d0 + 6) * VSTR2 + kp] = prmt(ah.w, bh.w, 0x5410);
            sVh[(d0 + 7) * VSTR2 + kp] = prmt(ah.w, bh.w, 0x7632);
            sVl[(d0 + 0) * VSTR2 + kp] = prmt(al.x, bl.x, 0x5410);
            sVl[(d0 + 1) * VSTR2 + kp] = prmt(al.x, bl.x, 0x7632);
            sVl[(d0 + 2) * VSTR2 + kp] = prmt(al.y, bl.y, 0x5410);
            sVl[(d0 + 3) * VSTR2 + kp] = prmt(al.y, bl.y, 0x7632);
            sVl[(d0 + 4) * VSTR2 + kp] = prmt(al.z, bl.z, 0x5410);
            sVl[(d0 + 5) * VSTR2 + kp] = prmt(al.z, bl.z, 0x7632);
            sVl[(d0 + 6) * VSTR2 + kp] = prmt(al.w, bl.w, 0x5410);
            sVl[(d0 + 7) * VSTR2 + kp] = prmt(al.w, bl.w, 0x7632);
        }
        __syncthreads();

        float s[6][4];
        #pragma unroll
        for (int nt = 0; nt < 6; nt++)
            #pragma unroll
            for (int i = 0; i < 4; i++) s[nt][i] = 0.f;

        #pragma unroll
        for (int ks = 0; ks < 4; ks++) {
            uint32_t ah[4], al[4];
            ldsm_x4(ah, qh_base + ks * 32);
            ldsm_x4(al, ql_base + ks * 32);
            #pragma unroll
            for (int ntp = 0; ntp < 3; ntp++) {
                uint32_t bh[4], bl[4];
                ldsm_x4(bh, kh_base + ks * 32 + ntp * (16 * KSTR2 * 4));
                ldsm_x4(bl, kl_base + ks * 32 + ntp * (16 * KSTR2 * 4));
                mma_bf16(s[2 * ntp],     ah, bh);
                mma_bf16(s[2 * ntp],     ah, bl);
                mma_bf16(s[2 * ntp],     al, bh);
                mma_bf16(s[2 * ntp + 1], ah, bh + 2);
                mma_bf16(s[2 * ntp + 1], ah, bl + 2);
                mma_bf16(s[2 * ntp + 1], al, bh + 2);
            }
        }

        const int trow0 = t0 + m0 + gr;
        const int trow1 = trow0 + 8;
        #pragma unroll
        for (int nt = 0; nt < 6; nt++) {
            int T0 = cs + nbase + nt * 8 + 2 * qc;
            int T1 = T0 + 1;
            bool in0 = (T0 >= 0) && (T0 < S_LEN);
            bool in1 = (T1 >= 0) && (T1 < S_LEN);
            int a00 = abs(trow0 - T0), a01 = abs(trow0 - T1);
            int a10 = abs(trow1 - T0), a11 = abs(trow1 - T1);
            float p00 = (in0 && a00 <= HALF)
                ? __expf(fmaf(s[nt][0], 0.125f, fmaf(-slope, (float)a00, -FIXM))) : 0.f;
            float p01 = (in1 && a01 <= HALF)
                ? __expf(fmaf(s[nt][1], 0.125f, fmaf(-slope, (float)a01, -FIXM))) : 0.f;
            float p10 = (in0 && a10 <= HALF)
                ? __expf(fmaf(s[nt][2], 0.125f, fmaf(-slope, (float)a10, -FIXM))) : 0.f;
            float p11 = (in1 && a11 <= HALF)
                ? __expf(fmaf(s[nt][3], 0.125f, fmaf(-slope, (float)a11, -FIXM))) : 0.f;
            sum0 += p00 + p01;
            sum1 += p10 + p11;
            int kp = wn * 24 + nt * 4 + qc;
            uint32_t hp, lp;
            split2(p00, p01, hp, lp);
            sPh[(m0 + gr) * PSTR2 + kp] = hp;
            sPl[(m0 + gr) * PSTR2 + kp] = lp;
            split2(p10, p11, hp, lp);
            sPh[(m0 + gr + 8) * PSTR2 + kp] = hp;
            sPl[(m0 + gr + 8) * PSTR2 + kp] = lp;
        }
        __syncthreads();

        #pragma unroll
        for (int ks = 0; ks < 6; ks++) {
            uint32_t ah[4], al[4];
            ldsm_x4(ah, ph_base + ks * 32);
            ldsm_x4(al, pl_base + ks * 32);
            #pragma unroll
            for (int ntp = 0; ntp < 2; ntp++) {
                uint32_t bh[4], bl[4];
                ldsm_x4(bh, vh_base + ks * 32 + ntp * (16 * VSTR2 * 4));
                ldsm_x4(bl, vl_base + ks * 32 + ntp * (16 * VSTR2 * 4));
                mma_bf16(o[2 * ntp],     ah, bh);
                mma_bf16(o[2 * ntp],     ah, bl);
                mma_bf16(o[2 * ntp],     al, bh);
                mma_bf16(o[2 * ntp + 1], ah, bh + 2);
                mma_bf16(o[2 * ntp + 1], ah, bl + 2);
                mma_bf16(o[2 * ntp + 1], al, bh + 2);
            }
        }
        __syncthreads();
    }

    sum0 += __shfl_xor_sync(0xffffffffu, sum0, 1);
    sum0 += __shfl_xor_sync(0xffffffffu, sum0, 2);
    sum1 += __shfl_xor_sync(0xffffffffu, sum1, 1);
    sum1 += __shfl_xor_sync(0xffffffffu, sum1, 2);
    if (qc == 0) {
        red[(m0 + gr) * 2 + wn] = sum0;
        red[(m0 + gr + 8) * 2 + wn] = sum1;
    }
    __syncthreads();

    // ---- normalize and write PRE-SPLIT output planes ----
    const int trow0 = t0 + m0 + gr;
    const float inv0 = 1.0f / (red[(m0 + gr) * 2] + red[(m0 + gr) * 2 + 1]);
    const float inv1 = 1.0f / (red[(m0 + gr + 8) * 2] + red[(m0 + gr + 8) * 2 + 1]);
    const size_t orow0 = (size_t)(b * S_LEN + trow0) * KPR;
    const size_t orow1 = orow0 + (size_t)8 * KPR;
    #pragma unroll
    for (int nt = 0; nt < 4; nt++) {
        int d = nb2 + nt * 8 + 2 * qc;
        int kp = (h * DH + d) >> 1;
        uint32_t hp, lp;
        split2(o[nt][0] * inv0, o[nt][1] * inv0, hp, lp);
        g_ath[orow0 + kp] = hp;
        g_atl[orow0 + kp] = lp;
        split2(o[nt][2] * inv1, o[nt][3] * inv1, hp, lp);
        g_ath[orow1 + kp] = hp;
        g_atl[orow1 + kp] = lp;
    }
}

// ---------------------------------------------------------------------------
extern "C" void kernel_launch(void* const* d_in, const int* in_sizes, int n_in,
                              void* d_out, int out_size)
{
    (void)in_sizes; (void)n_in; (void)out_size;
    const float* inputs_q  = (const float*)d_in[0];
    const float* inputs_kv = (const float*)d_in[1];
    const float* w_q = (const float*)d_in[2];
    const float* w_k = (const float*)d_in[3];
    const float* w_v = (const float*)d_in[4];
    const float* w_o = (const float*)d_in[5];
    float* out = (float*)d_out;

    uint32_t *iqh, *iql, *ikh, *ikl;
    uint32_t *wqh, *wql, *wkh, *wkl, *wvh, *wvl, *woh, *wol;
    uint32_t *qh, *ql, *kh, *kl, *vh, *vl, *ath, *atl;
    cudaGetSymbolAddress((void**)&iqh, g_iqh);
    cudaGetSymbolAddress((void**)&iql, g_iql);
    cudaGetSymbolAddress((void**)&ikh, g_ikh);
    cudaGetSymbolAddress((void**)&ikl, g_ikl);
    cudaGetSymbolAddress((void**)&wqh, g_wqh);
    cudaGetSymbolAddress((void**)&wql, g_wql);
    cudaGetSymbolAddress((void**)&wkh, g_wkh);
    cudaGetSymbolAddress((void**)&wkl, g_wkl);
    cudaGetSymbolAddress((void**)&wvh, g_wvh);
    cudaGetSymbolAddress((void**)&wvl, g_wvl);
    cudaGetSymbolAddress((void**)&woh, g_woh);
    cudaGetSymbolAddress((void**)&wol, g_wol);
    cudaGetSymbolAddress((void**)&qh, g_qh);
    cudaGetSymbolAddress((void**)&ql, g_ql);
    cudaGetSymbolAddress((void**)&kh, g_kh);
    cudaGetSymbolAddress((void**)&kl, g_kl);
    cudaGetSymbolAddress((void**)&vh, g_vh);
    cudaGetSymbolAddress((void**)&vl, g_vl);
    cudaGetSymbolAddress((void**)&ath, g_ath);
    cudaGetSymbolAddress((void**)&atl, g_atl);

    cudaFuncSetAttribute(gemm_ps_kernel<true>,
                         cudaFuncAttributeMaxDynamicSharedMemorySize,
                         GEMM_SMEM_BYTES);
    cudaFuncSetAttribute(gemm_ps_kernel<false>,
                         cudaFuncAttributeMaxDynamicSharedMemorySize,
                         GEMM_SMEM_BYTES);
    cudaFuncSetAttribute(attn_tc_kernel,
                         cudaFuncAttributeMaxDynamicSharedMemorySize,
                         ATTN_SMEM_BYTES);

    // Pre-split inputs (A-type) and weights (B-type)
    const int n4 = ROWS * EMB / 4;   // 1,048,576
    presplit_pairs<<<n4 / 256, 256>>>((const float4*)inputs_q,
                                      (uint2*)iqh, (uint2*)iql, n4);
    presplit_pairs<<<n4 / 256, 256>>>((const float4*)inputs_kv,
                                      (uint2*)ikh, (uint2*)ikl, n4);
    presplit_wB<<<128, 256>>>(w_q, wqh, wql);
    presplit_wB<<<128, 256>>>(w_k, wkh, wkl);
    presplit_wB<<<128, 256>>>(w_v, wvh, wvl);
    presplit_wB<<<128, 256>>>(w_o, woh, wol);

    dim3 gGemm(EMB / GBN, ROWS / GBM);   // (4, 64)
    gemm_ps_kernel<true><<<gGemm, 256, GEMM_SMEM_BYTES>>>(
        iqh, iql, wqh, wql, nullptr, qh, ql);
    gemm_ps_kernel<true><<<gGemm, 256, GEMM_SMEM_BYTES>>>(
        ikh, ikl, wkh, wkl, nullptr, kh, kl);
    gemm_ps_kernel<true><<<gGemm, 256, GEMM_SMEM_BYTES>>>(
        ikh, ikl, wvh, wvl, nullptr, vh, vl);

    dim3 gAttn(S_LEN / AQT, NH, BATCH);  // (64, 8, 2)
    attn_tc_kernel<<<gAttn, ATHREADS, ATTN_SMEM_BYTES>>>();

    gemm_ps_kernel<false><<<gGemm, 256, GEMM_SMEM_BYTES>>>(
        ath, atl, woh, wol, out, nullptr, nullptr);
}

// round 14
// speedup vs baseline: 1.1038x; 1.1023x over previous
#include <cuda_runtime.h>
#include <math.h>
#include <stdint.h>

// Problem constants
constexpr int S_LEN = 4096;
constexpr int BATCH = 2;
constexpr int EMB   = 512;   // E and also H*D
constexpr int NH    = 8;
constexpr int DH    = 64;
constexpr int HALF  = 256;   // sliding window half-width
constexpr int ROWS  = BATCH * S_LEN;  // 8192
constexpr int KPR   = EMB / 2;        // 256 kpairs per row

// Scratch (allocation-free rule: __device__ globals)
__device__ uint32_t g_qh[(size_t)ROWS * KPR];
__device__ uint32_t g_ql[(size_t)ROWS * KPR];
__device__ uint32_t g_kh[(size_t)ROWS * KPR];
__device__ uint32_t g_kl[(size_t)ROWS * KPR];
__device__ uint32_t g_vh[(size_t)ROWS * KPR];
__device__ uint32_t g_vl[(size_t)ROWS * KPR];
__device__ float    g_att[(size_t)ROWS * EMB];

// ---------------------------------------------------------------------------
// helpers
// ---------------------------------------------------------------------------
__device__ __forceinline__ void split2(float x0, float x1,
                                       uint32_t& hp, uint32_t& lp) {
    asm("cvt.rn.bf16x2.f32 %0, %1, %2;" : "=r"(hp) : "f"(x1), "f"(x0));
    float h0 = __uint_as_float(hp << 16);
    float h1 = __uint_as_float(hp & 0xffff0000u);
    float r0 = x0 - h0;
    float r1 = x1 - h1;
    asm("cvt.rn.bf16x2.f32 %0, %1, %2;" : "=r"(lp) : "f"(r1), "f"(r0));
}

__device__ __forceinline__ void mma_bf16(float d[4], const uint32_t a[4],
                                         const uint32_t b[2]) {
    asm volatile(
        "mma.sync.aligned.m16n8k16.row.col.f32.bf16.bf16.f32 "
        "{%0,%1,%2,%3}, {%4,%5,%6,%7}, {%8,%9}, {%0,%1,%2,%3};\n"
        : "+f"(d[0]), "+f"(d[1]), "+f"(d[2]), "+f"(d[3])
        : "r"(a[0]), "r"(a[1]), "r"(a[2]), "r"(a[3]), "r"(b[0]), "r"(b[1]));
}

__device__ __forceinline__ void ldsm_x4(uint32_t r[4], uint32_t addr) {
    asm volatile(
        "ldmatrix.sync.aligned.m8n8.x4.shared.b16 {%0,%1,%2,%3}, [%4];"
        : "=r"(r[0]), "=r"(r[1]), "=r"(r[2]), "=r"(r[3]) : "r"(addr));
}

__device__ __forceinline__ uint32_t smem_u32(const void* p) {
    return (uint32_t)__cvta_generic_to_shared(p);
}

__device__ __forceinline__ uint32_t prmt(uint32_t a, uint32_t b, uint32_t s) {
    uint32_t d;
    asm("prmt.b32 %0, %1, %2, %3;" : "=r"(d) : "r"(a), "r"(b), "r"(s));
    return d;
}

// ---------------------------------------------------------------------------
// Split-bf16 tensor-core GEMM (R9-validated, near mma.sync roofline).
// C[M,N] = A[M,K] @ B[K,N], row-major. 128x128 CTA tile, BK=32, 256 thr.
// SPLIT_OUT=true writes bf16x2 hi/lo planes, else fp32.
// ---------------------------------------------------------------------------
constexpr int GBM = 128, GBN = 128, GBK = 32;
constexpr int KP  = GBK / 2;
constexpr int ASTR = 20;
constexpr int BSTR = 136;
constexpr int A_STAGE = GBM * ASTR;
constexpr int B_STAGE = KP * BSTR;
constexpr int GEMM_SMEM_BYTES = (4 * A_STAGE + 4 * B_STAGE) * 4;

template <bool SPLIT_OUT>
__global__ __launch_bounds__(256, 1) void gemm_bf16_kernel(
    const float* __restrict__ A, const float* __restrict__ B,
    float* __restrict__ C, uint32_t* __restrict__ Ch, uint32_t* __restrict__ Cl,
    int M, int N, int K)
{
    extern __shared__ uint32_t sm[];
    uint32_t* sAh = sm;
    uint32_t* sAl = sAh + 2 * A_STAGE;
    uint32_t* sBh = sAl + 2 * A_STAGE;
    uint32_t* sBl = sBh + 2 * B_STAGE;

    const int tid  = threadIdx.x;
    const int lane = tid & 31;
    const int wid  = tid >> 5;
    const int m_base = (wid >> 2) * 64;
    const int n_base = (wid & 3) * 32;
    const int row0 = blockIdx.y * GBM;
    const int col0 = blockIdx.x * GBN;

    const int arow  = tid >> 2;
    const int acolg = (tid & 3) * 8;
    const int akp   = (tid & 3) * 4;
    const int brow = tid >> 5;
    const int bcol = (tid & 31) * 4;

    const float* pA0 = A + (size_t)(row0 + arow) * K + acolg;
    const float* pA1 = A + (size_t)(row0 + arow + 64) * K + acolg;
    const float* pB00 = B + (size_t)(2 * brow) * N + col0 + bcol;
    const float* pB01 = B + (size_t)(2 * brow + 1) * N + col0 + bcol;
    const float* pB10 = B + (size_t)(2 * (brow + 8)) * N + col0 + bcol;
    const float* pB11 = B + (size_t)(2 * (brow + 8) + 1) * N + col0 + bcol;

    const int NT = K / GBK;

    float acc[4][4][4] = {};
    float4 fa00, fa01, fa10, fa11;
    float4 fb00, fb01, fb10, fb11;

    #define STORE_A(dsth, dstl, r, v0, v1)                                    \
        {                                                                     \
            uint32_t h0, l0, h1, l1, h2, l2, h3, l3;                          \
            split2((v0).x, (v0).y, h0, l0);                                   \
            split2((v0).z, (v0).w, h1, l1);                                   \
            split2((v1).x, (v1).y, h2, l2);                                   \
            split2((v1).z, (v1).w, h3, l3);                                   \
            *(uint4*)&(dsth)[(r) * ASTR + akp] = make_uint4(h0, h1, h2, h3);  \
            *(uint4*)&(dstl)[(r) * ASTR + akp] = make_uint4(l0, l1, l2, l3);  \
        }

    #define STORE_B(dsth, dstl, kp, v0, v1)                                   \
        {                                                                     \
            uint32_t h0, l0, h1, l1, h2, l2, h3, l3;                          \
            split2((v0).x, (v1).x, h0, l0);                                   \
            split2((v0).y, (v1).y, h1, l1);                                   \
            split2((v0).z, (v1).z, h2, l2);                                   \
            split2((v0).w, (v1).w, h3, l3);                                   \
            *(uint4*)&(dsth)[(kp) * BSTR + bcol] = make_uint4(h0, h1, h2, h3);\
            *(uint4*)&(dstl)[(kp) * BSTR + bcol] = make_uint4(l0, l1, l2, l3);\
        }

    fa00 = *(const float4*)(pA0);
    fa01 = *(const float4*)(pA0 + 4);
    fa10 = *(const float4*)(pA1);
    fa11 = *(const float4*)(pA1 + 4);
    fb00 = *(const float4*)(pB00);
    fb01 = *(const float4*)(pB01);
    fb10 = *(const float4*)(pB10);
    fb11 = *(const float4*)(pB11);

    STORE_A(sAh, sAl, arow, fa00, fa01);
    STORE_A(sAh, sAl, arow + 64, fa10, fa11);
    STORE_B(sBh, sBl, brow, fb00, fb01);
    STORE_B(sBh, sBl, brow + 8, fb10, fb11);
    __syncthreads();

    const int gr = lane >> 2;
    const int qc = lane & 3;

    for (int kt = 0; kt < NT; kt++) {
        if (kt + 1 < NT) {
            int ko = (kt + 1) * GBK;
            fa00 = *(const float4*)(pA0 + ko);
            fa01 = *(const float4*)(pA0 + ko + 4);
            fa10 = *(const float4*)(pA1 + ko);
            fa11 = *(const float4*)(pA1 + ko + 4);
            fb00 = *(const float4*)(pB00 + (size_t)ko * N);
            fb01 = *(const float4*)(pB01 + (size_t)ko * N);
            fb10 = *(const float4*)(pB10 + (size_t)ko * N);
            fb11 = *(const float4*)(pB11 + (size_t)ko * N);
        }

        const uint32_t* Ah = sAh + (kt & 1) * A_STAGE;
        const uint32_t* Al = sAl + (kt & 1) * A_STAGE;
        const uint32_t* Bh = sBh + (kt & 1) * B_STAGE;
        const uint32_t* Bl = sBl + (kt & 1) * B_STAGE;

        #pragma unroll
        for (int ks = 0; ks < 2; ks++) {
            const int kp0 = ks * 8 + qc;
            uint32_t ah[4][4], al[4][4], bh[4][2], bl[4][2];
            #pragma unroll
            for (int mt = 0; mt < 4; mt++) {
                const int m = m_base + mt * 16 + gr;
                ah[mt][0] = Ah[m * ASTR + kp0];
                ah[mt][1] = Ah[(m + 8) * ASTR + kp0];
                ah[mt][2] = Ah[m * ASTR + kp0 + 4];
                ah[mt][3] = Ah[(m + 8) * ASTR + kp0 + 4];
                al[mt][0] = Al[m * ASTR + kp0];
                al[mt][1] = Al[(m + 8) * ASTR + kp0];
                al[mt][2] = Al[m * ASTR + kp0 + 4];
                al[mt][3] = Al[(m + 8) * ASTR + kp0 + 4];
            }
            #pragma unroll
            for (int nt = 0; nt < 4; nt++) {
                const int n = n_base + nt * 8 + gr;
                bh[nt][0] = Bh[kp0 * BSTR + n];
                bh[nt][1] = Bh[(kp0 + 4) * BSTR + n];
                bl[nt][0] = Bl[kp0 * BSTR + n];
                bl[nt][1] = Bl[(kp0 + 4) * BSTR + n];
            }
            #pragma unroll
            for (int mt = 0; mt < 4; mt++)
                #pragma unroll
                for (int nt = 0; nt < 4; nt++) {
                    mma_bf16(acc[mt][nt], ah[mt], bh[nt]);
                    mma_bf16(acc[mt][nt], ah[mt], bl[nt]);
                    mma_bf16(acc[mt][nt], al[mt], bh[nt]);
                }
        }

        if (kt + 1 < NT) {
            uint32_t* dAh = sAh + ((kt + 1) & 1) * A_STAGE;
            uint32_t* dAl = sAl + ((kt + 1) & 1) * A_STAGE;
            uint32_t* dBh = sBh + ((kt + 1) & 1) * B_STAGE;
            uint32_t* dBl = sBl + ((kt + 1) & 1) * B_STAGE;
            STORE_A(dAh, dAl, arow, fa00, fa01);
            STORE_A(dAh, dAl, arow + 64, fa10, fa11);
            STORE_B(dBh, dBl, brow, fb00, fb01);
            STORE_B(dBh, dBl, brow + 8, fb10, fb11);
        }
        __syncthreads();
    }
    #undef STORE_A
    #undef STORE_B

    #pragma unroll
    for (int mt = 0; mt < 4; mt++) {
        #pragma unroll
        for (int nt = 0; nt < 4; nt++) {
            int r = row0 + m_base + mt * 16 + gr;
            int c = col0 + n_base + nt * 8 + 2 * qc;
            if constexpr (SPLIT_OUT) {
                int kp = c >> 1;
                uint32_t hp, lp;
                split2(acc[mt][nt][0], acc[mt][nt][1], hp, lp);
                Ch[(size_t)r * KPR + kp] = hp;
                Cl[(size_t)r * KPR + kp] = lp;
                split2(acc[mt][nt][2], acc[mt][nt][3], hp, lp);
                Ch[(size_t)(r + 8) * KPR + kp] = hp;
                Cl[(size_t)(r + 8) * KPR + kp] = lp;
            } else {
                *(float2*)&C[(size_t)r * N + c] =
                    make_float2(acc[mt][nt][0], acc[mt][nt][1]);
                *(float2*)&C[(size_t)(r + 8) * N + c] =
                    make_float2(acc[mt][nt][2], acc[mt][nt][3]);
            }
        }
    }
}

// ---------------------------------------------------------------------------
// Attention: split-bf16, ldmatrix, pre-split inputs, fixed-max softmax,
// REGISTER-RESIDENT P (S c-frag == PV a-frag; no smem P, 2 barriers/chunk).
// Each warp owns 48 keys x all 64 dims; wn=0/1 partial O reduced via smem.
// 256 threads, 6 chunks of 96 keys, 2 CTAs/SM.
// ---------------------------------------------------------------------------
constexpr int AQT = 64;
constexpr int AKT = 96;
constexpr int NCHUNK = 6;
constexpr int QSTR2 = 36;
constexpr int KSTR2 = 36;
constexpr int VSTR2 = 52;
constexpr int ATHREADS = 256;
constexpr float FIXM = 12.0f;

constexpr int OFF_QH = 0;
constexpr int OFF_QL = OFF_QH + AQT * QSTR2;        // 2304
constexpr int OFF_KH = OFF_QL + AQT * QSTR2;        // 4608
constexpr int OFF_KL = OFF_KH + AKT * KSTR2;        // 8064
constexpr int OFF_VH = OFF_KL + AKT * KSTR2;        // 11520
constexpr int OFF_VL = OFF_VH + 64 * VSTR2;         // 14848
constexpr int OFF_RED = OFF_VL + 64 * VSTR2;        // 18176 (float[128])
constexpr int OFF_ORED = OFF_RED + 128;             // 18304 (float[64][66])
constexpr int ATTN_SMEM_WORDS = OFF_ORED + 64 * 66; // 22528
constexpr int ATTN_SMEM_BYTES = ATTN_SMEM_WORDS * 4;  // 90112

__global__ __launch_bounds__(ATHREADS, 2) void attn_tc_kernel()
{
    extern __shared__ uint32_t sm[];
    uint32_t* sQh = sm + OFF_QH;
    uint32_t* sQl = sm + OFF_QL;
    uint32_t* sKh = sm + OFF_KH;
    uint32_t* sKl = sm + OFF_KL;
    uint32_t* sVh = sm + OFF_VH;
    uint32_t* sVl = sm + OFF_VL;
    float* red  = (float*)(sm + OFF_RED);
    float* ored = (float*)(sm + OFF_ORED);

    const int tid  = threadIdx.x;
    const int lane = tid & 31;
    const int wid  = tid >> 5;     // 0..7
    const int gr = lane >> 2;
    const int qc = lane & 3;
    const int wm = wid >> 1;       // 0..3
    const int wn = wid & 1;        // 0..1
    const int m0 = wm * 16;

    const int t0 = blockIdx.x * AQT;
    const int h  = blockIdx.y;
    const int b  = blockIdx.z;
    const float slope = exp2f(-(float)(h + 1));

    const uint32_t* Qh_p = g_qh + ((size_t)(b * S_LEN + t0)) * KPR + h * 32;
    const uint32_t* Ql_p = g_ql + ((size_t)(b * S_LEN + t0)) * KPR + h * 32;
    const uint32_t* Kh_p = g_kh + ((size_t)b * S_LEN) * KPR + h * 32;
    const uint32_t* Kl_p = g_kl + ((size_t)b * S_LEN) * KPR + h * 32;
    const uint32_t* Vh_p = g_vh + ((size_t)b * S_LEN) * KPR + h * 32;
    const uint32_t* Vl_p = g_vl + ((size_t)b * S_LEN) * KPR + h * 32;
    float* Ob = g_att + (size_t)b * S_LEN * EMB + h * DH;

    const int lrow8  = (lane & 7);
    const int lmsel  = (lane >> 3) & 1;
    const int lhsel  = (lane >> 4) & 1;

    // A-frag (Q)
    const uint32_t qh_base = smem_u32(sQh) +
        (((m0 + lrow8 + lmsel * 8) * QSTR2) + lhsel * 4) * 4;
    const uint32_t ql_base = qh_base + (OFF_QL - OFF_QH) * 4;
    // B-frag (K): warp covers keys [wn*48, wn*48+48)
    const int nbase = wn * 48;
    const uint32_t kh_base = smem_u32(sKh) +
        (((nbase + lrow8 + lhsel * 8) * KSTR2) + lmsel * 4) * 4;
    const uint32_t kl_base = kh_base + (OFF_KL - OFF_KH) * 4;
    // B-frag (V): rows = d (all 64, via dt), cols = warp's keypairs wn*24..
    const uint32_t vh_base = smem_u32(sVh) +
        (((lrow8 + lhsel * 8) * VSTR2) + wn * 24 + lmsel * 4) * 4;
    const uint32_t vl_base = vh_base + (OFF_VL - OFF_VH) * 4;

    // Load Q tile (pure copy of pre-split planes)
    for (int idx = tid; idx < 512; idx += ATHREADS) {
        int q = idx >> 3;
        int j = idx & 7;
        uint4 vh = *(const uint4*)&Qh_p[(size_t)q * KPR + j * 4];
        uint4 vl = *(const uint4*)&Ql_p[(size_t)q * KPR + j * 4];
        *(uint4*)&sQh[q * QSTR2 + j * 4] = vh;
        *(uint4*)&sQl[q * QSTR2 + j * 4] = vl;
    }

    float o[8][4] = {};      // partial O: 16 q x 64 d (this warp's 48 keys)
    float sum0 = 0.f, sum1 = 0.f;

    const int base = t0 - HALF;

    #pragma unroll 1
    for (int c = 0; c < NCHUNK; c++) {
        const int cs = base + c * AKT;
        if (cs + AKT <= 0 || cs >= S_LEN) continue;

        // ---- K chunk: pure copy ----
        for (int idx = tid; idx < 768; idx += ATHREADS) {
            int key = idx >> 3;
            int j = idx & 7;
            int T = cs + key;
            uint4 vh = make_uint4(0, 0, 0, 0);
            uint4 vl = make_uint4(0, 0, 0, 0);
            if (T >= 0 && T < S_LEN) {
                vh = *(const uint4*)&Kh_p[(size_t)T * KPR + j * 4];
                vl = *(const uint4*)&Kl_p[(size_t)T * KPR + j * 4];
            }
            *(uint4*)&sKh[key * KSTR2 + j * 4] = vh;
            *(uint4*)&sKl[key * KSTR2 + j * 4] = vl;
        }
        // ---- V chunk: load 2 rows, PRMT-transpose into [d][kp] ----
        for (int idx = tid; idx < 384; idx += ATHREADS) {
            int kp = idx >> 3;
            int j = idx & 7;
            int T0 = cs + 2 * kp, T1 = T0 + 1;
            uint4 ah = make_uint4(0, 0, 0, 0), al = make_uint4(0, 0, 0, 0);
            uint4 bh = make_uint4(0, 0, 0, 0), bl = make_uint4(0, 0, 0, 0);
            if (T0 >= 0 && T0 < S_LEN) {
                ah = *(const uint4*)&Vh_p[(size_t)T0 * KPR + j * 4];
                al = *(const uint4*)&Vl_p[(size_t)T0 * KPR + j * 4];
            }
            if (T1 >= 0 && T1 < S_LEN) {
                bh = *(const uint4*)&Vh_p[(size_t)T1 * KPR + j * 4];
                bl = *(const uint4*)&Vl_p[(size_t)T1 * KPR + j * 4];
            }
            int d0 = 8 * j;
            sVh[(d0 + 0) * VSTR2 + kp] = prmt(ah.x, bh.x, 0x5410);
            sVh[(d0 + 1) * VSTR2 + kp] = prmt(ah.x, bh.x, 0x7632);
            sVh[(d0 + 2) * VSTR2 + kp] = prmt(ah.y, bh.y, 0x5410);
            sVh[(d0 + 3) * VSTR2 + kp] = prmt(ah.y, bh.y, 0x7632);
            sVh[(d0 + 4) * VSTR2 + kp] = prmt(ah.z, bh.z, 0x5410);
            sVh[(d0 + 5) * VSTR2 + kp] = prmt(ah.z, bh.z, 0x7632);
            sVh[(d0 + 6) * VSTR2 + kp] = prmt(ah.w, bh.w, 0x5410);
            sVh[(d0 + 7) * VSTR2 + kp] = prmt(ah.w, bh.w, 0x7632);
            sVl[(d0 + 0) * VSTR2 + kp] = prmt(al.x, bl.x, 0x5410);
            sVl[(d0 + 1) * VSTR2 + kp] = prmt(al.x, bl.x, 0x7632);
            sVl[(d0 + 2) * VSTR2 + kp] = prmt(al.y, bl.y, 0x5410);
            sVl[(d0 + 3) * VSTR2 + kp] = prmt(al.y, bl.y, 0x7632);
            sVl[(d0 + 4) * VSTR2 + kp] = prmt(al.z, bl.z, 0x5410);
            sVl[(d0 + 5) * VSTR2 + kp] = prmt(al.z, bl.z, 0x7632);
            sVl[(d0 + 6) * VSTR2 + kp] = prmt(al.w, bl.w, 0x5410);
            sVl[(d0 + 7) * VSTR2 + kp] = prmt(al.w, bl.w, 0x7632);
        }
        __syncthreads();

        // ---- S = Q @ K^T : warp tile 16 x 48 ----
        float s[6][4];
        #pragma unroll
        for (int nt = 0; nt < 6; nt++)
            #pragma unroll
            for (int i = 0; i < 4; i++) s[nt][i] = 0.f;

        #pragma unroll
        for (int ks = 0; ks < 4; ks++) {
            uint32_t ah[4], al[4];
            ldsm_x4(ah, qh_base + ks * 32);
            ldsm_x4(al, ql_base + ks * 32);
            #pragma unroll
            for (int ntp = 0; ntp < 3; ntp++) {
                uint32_t bh[4], bl[4];
                ldsm_x4(bh, kh_base + ks * 32 + ntp * (16 * KSTR2 * 4));
                ldsm_x4(bl, kl_base + ks * 32 + ntp * (16 * KSTR2 * 4));
                mma_bf16(s[2 * ntp],     ah, bh);
                mma_bf16(s[2 * ntp],     ah, bl);
                mma_bf16(s[2 * ntp],     al, bh);
                mma_bf16(s[2 * ntp + 1], ah, bh + 2);
                mma_bf16(s[2 * ntp + 1], ah, bl + 2);
                mma_bf16(s[2 * ntp + 1], al, bh + 2);
            }
        }

        // ---- fixed-max softmax -> pack P directly into PV A-fragments ----
        const int trow0 = t0 + m0 + gr;
        const int trow1 = trow0 + 8;
        uint32_t pah[3][4], pal[3][4];
        #pragma unroll
        for (int nt = 0; nt < 6; nt++) {
            int T0 = cs + nbase + nt * 8 + 2 * qc;
            int T1 = T0 + 1;
            bool in0 = (T0 >= 0) && (T0 < S_LEN);
            bool in1 = (T1 >= 0) && (T1 < S_LEN);
            int a00 = abs(trow0 - T0), a01 = abs(trow0 - T1);
            int a10 = abs(trow1 - T0), a11 = abs(trow1 - T1);
            float p00 = (in0 && a00 <= HALF)
                ? __expf(fmaf(s[nt][0], 0.125f, fmaf(-slope, (float)a00, -FIXM))) : 0.f;
            float p01 = (in1 && a01 <= HALF)
                ? __expf(fmaf(s[nt][1], 0.125f, fmaf(-slope, (float)a01, -FIXM))) : 0.f;
            float p10 = (in0 && a10 <= HALF)
                ? __expf(fmaf(s[nt][2], 0.125f, fmaf(-slope, (float)a10, -FIXM))) : 0.f;
            float p11 = (in1 && a11 <= HALF)
                ? __expf(fmaf(s[nt][3], 0.125f, fmaf(-slope, (float)a11, -FIXM))) : 0.f;
            sum0 += p00 + p01;
            sum1 += p10 + p11;
            // c-frag (m16n8) == a-frag (m16n8k16) halves:
            // a0/a1 from even nt (keys 0..7 of k16), a2/a3 from odd nt.
            int ks = nt >> 1;
            int half = (nt & 1) * 2;
            uint32_t hp, lp;
            split2(p00, p01, hp, lp);
            pah[ks][half + 0] = hp;  pal[ks][half + 0] = lp;
            split2(p10, p11, hp, lp);
            pah[ks][half + 1] = hp;  pal[ks][half + 1] = lp;
        }

        // ---- O += P @ V : this warp's 48 keys x all 64 dims ----
        #pragma unroll
        for (int ks = 0; ks < 3; ks++) {
            #pragma unroll
            for (int dt = 0; dt < 4; dt++) {
                uint32_t bh[4], bl[4];
                uint32_t off = (uint32_t)(dt * 16 * VSTR2 * 4 + ks * 32);
                ldsm_x4(bh, vh_base + off);
                ldsm_x4(bl, vl_base + off);
                mma_bf16(o[2 * dt],     pah[ks], bh);
                mma_bf16(o[2 * dt],     pah[ks], bl);
                mma_bf16(o[2 * dt],     pal[ks], bh);
                mma_bf16(o[2 * dt + 1], pah[ks], bh + 2);
                mma_bf16(o[2 * dt + 1], pah[ks], bl + 2);
                mma_bf16(o[2 * dt + 1], pal[ks], bh + 2);
            }
        }
        __syncthreads();
    }

    // ---- reduce across wn pairs + row sums, normalize, write ----
    sum0 += __shfl_xor_sync(0xffffffffu, sum0, 1);
    sum0 += __shfl_xor_sync(0xffffffffu, sum0, 2);
    sum1 += __shfl_xor_sync(0xffffffffu, sum1, 1);
    sum1 += __shfl_xor_sync(0xffffffffu, sum1, 2);
    if (qc == 0) {
        red[(m0 + gr) * 2 + wn] = sum0;
        red[(m0 + gr + 8) * 2 + wn] = sum1;
    }
    if (wn == 1) {
        #pragma unroll
        for (int nt = 0; nt < 8; nt++) {
            int d = nt * 8 + 2 * qc;
            *(float2*)&ored[(m0 + gr) * 66 + d] = make_float2(o[nt][0], o[nt][1]);
            *(float2*)&ored[(m0 + gr + 8) * 66 + d] = make_float2(o[nt][2], o[nt][3]);
        }
    }
    __syncthreads();

    if (wn == 0) {
        const int trow0 = t0 + m0 + gr;
        const float inv0 = 1.0f / (red[(m0 + gr) * 2] + red[(m0 + gr) * 2 + 1]);
        const float inv1 = 1.0f / (red[(m0 + gr + 8) * 2] + red[(m0 + gr + 8) * 2 + 1]);
        #pragma unroll
        for (int nt = 0; nt < 8; nt++) {
            int d = nt * 8 + 2 * qc;
            float2 p0 = *(float2*)&ored[(m0 + gr) * 66 + d];
            float2 p1 = *(float2*)&ored[(m0 + gr + 8) * 66 + d];
            *(float2*)&Ob[(size_t)trow0 * EMB + d] =
                make_float2((o[nt][0] + p0.x) * inv0, (o[nt][1] + p0.y) * inv0);
            *(float2*)&Ob[(size_t)(trow0 + 8) * EMB + d] =
                make_float2((o[nt][2] + p1.x) * inv1, (o[nt][3] + p1.y) * inv1);
        }
    }
}

// ---------------------------------------------------------------------------
extern "C" void kernel_launch(void* const* d_in, const int* in_sizes, int n_in,
                              void* d_out, int out_size)
{
    (void)in_sizes; (void)n_in; (void)out_size;
    const float* inputs_q  = (const float*)d_in[0];
    const float* inputs_kv = (const float*)d_in[1];
    const float* w_q = (const float*)d_in[2];
    const float* w_k = (const float*)d_in[3];
    const float* w_v = (const float*)d_in[4];
    const float* w_o = (const float*)d_in[5];
    float* out = (float*)d_out;

    uint32_t *qh, *ql, *kh, *kl, *vh, *vl;
    float* ab;
    cudaGetSymbolAddress((void**)&qh, g_qh);
    cudaGetSymbolAddress((void**)&ql, g_ql);
    cudaGetSymbolAddress((void**)&kh, g_kh);
    cudaGetSymbolAddress((void**)&kl, g_kl);
    cudaGetSymbolAddress((void**)&vh, g_vh);
    cudaGetSymbolAddress((void**)&vl, g_vl);
    cudaGetSymbolAddress((void**)&ab, g_att);

    cudaFuncSetAttribute(gemm_bf16_kernel<true>,
                         cudaFuncAttributeMaxDynamicSharedMemorySize,
                         GEMM_SMEM_BYTES);
    cudaFuncSetAttribute(gemm_bf16_kernel<false>,
                         cudaFuncAttributeMaxDynamicSharedMemorySize,
                         GEMM_SMEM_BYTES);
    cudaFuncSetAttribute(attn_tc_kernel,
                         cudaFuncAttributeMaxDynamicSharedMemorySize,
                         ATTN_SMEM_BYTES);

    dim3 gGemm(EMB / GBN, ROWS / GBM);   // (4, 64)
    gemm_bf16_kernel<true><<<gGemm, 256, GEMM_SMEM_BYTES>>>(
        inputs_q,  w_q, nullptr, qh, ql, ROWS, EMB, EMB);
    gemm_bf16_kernel<true><<<gGemm, 256, GEMM_SMEM_BYTES>>>(
        inputs_kv, w_k, nullptr, kh, kl, ROWS, EMB, EMB);
    gemm_bf16_kernel<true><<<gGemm, 256, GEMM_SMEM_BYTES>>>(
        inputs_kv, w_v, nullptr, vh, vl, ROWS, EMB, EMB);

    dim3 gAttn(S_LEN / AQT, NH, BATCH);  // (64, 8, 2)
    attn_tc_kernel<<<gAttn, ATHREADS, ATTN_SMEM_BYTES>>>();

    gemm_bf16_kernel<false><<<gGemm, 256, GEMM_SMEM_BYTES>>>(
        ab, w_o, out, nullptr, nullptr, ROWS, EMB, EMB);
}

// round 15
// speedup vs baseline: 1.1106x; 1.0061x over previous
#include <cuda_runtime.h>
#include <math.h>
#include <stdint.h>

// Problem constants
constexpr int S_LEN = 4096;
constexpr int BATCH = 2;
constexpr int EMB   = 512;   // E and also H*D
constexpr int NH    = 8;
constexpr int DH    = 64;
constexpr int HALF  = 256;   // sliding window half-width
constexpr int ROWS  = BATCH * S_LEN;  // 8192
constexpr int KPR   = EMB / 2;        // 256 kpairs per row

// Scratch (allocation-free rule: __device__ globals)
__device__ uint32_t g_qh[(size_t)ROWS * KPR];
__device__ uint32_t g_ql[(size_t)ROWS * KPR];
__device__ uint32_t g_kh[(size_t)ROWS * KPR];
__device__ uint32_t g_kl[(size_t)ROWS * KPR];
__device__ uint32_t g_vh[(size_t)ROWS * KPR];
__device__ uint32_t g_vl[(size_t)ROWS * KPR];
__device__ float    g_att[(size_t)ROWS * EMB];

// ---------------------------------------------------------------------------
// helpers
// ---------------------------------------------------------------------------
__device__ __forceinline__ void split2(float x0, float x1,
                                       uint32_t& hp, uint32_t& lp) {
    asm("cvt.rn.bf16x2.f32 %0, %1, %2;" : "=r"(hp) : "f"(x1), "f"(x0));
    float h0 = __uint_as_float(hp << 16);
    float h1 = __uint_as_float(hp & 0xffff0000u);
    float r0 = x0 - h0;
    float r1 = x1 - h1;
    asm("cvt.rn.bf16x2.f32 %0, %1, %2;" : "=r"(lp) : "f"(r1), "f"(r0));
}

__device__ __forceinline__ void mma_bf16(float d[4], const uint32_t a[4],
                                         const uint32_t b[2]) {
    asm volatile(
        "mma.sync.aligned.m16n8k16.row.col.f32.bf16.bf16.f32 "
        "{%0,%1,%2,%3}, {%4,%5,%6,%7}, {%8,%9}, {%0,%1,%2,%3};\n"
        : "+f"(d[0]), "+f"(d[1]), "+f"(d[2]), "+f"(d[3])
        : "r"(a[0]), "r"(a[1]), "r"(a[2]), "r"(a[3]), "r"(b[0]), "r"(b[1]));
}

__device__ __forceinline__ void ldsm_x4(uint32_t r[4], uint32_t addr) {
    asm volatile(
        "ldmatrix.sync.aligned.m8n8.x4.shared.b16 {%0,%1,%2,%3}, [%4];"
        : "=r"(r[0]), "=r"(r[1]), "=r"(r[2]), "=r"(r[3]) : "r"(addr));
}

__device__ __forceinline__ uint32_t smem_u32(const void* p) {
    return (uint32_t)__cvta_generic_to_shared(p);
}

__device__ __forceinline__ uint32_t prmt(uint32_t a, uint32_t b, uint32_t s) {
    uint32_t d;
    asm("prmt.b32 %0, %1, %2, %3;" : "=r"(d) : "r"(a), "r"(b), "r"(s));
    return d;
}

// ---------------------------------------------------------------------------
// Split-bf16 tensor-core GEMM, SINGLE-buffered smem + 2 CTAs/SM.
// Same 128x128 tile / BK=32 / warp layout as the R9-validated kernel; the
// double buffer is replaced by cross-CTA phase overlap (occupancy 2) and the
// grid (256 CTAs) now fits one wave of 296 slots.
// C[M,N] = A[M,K] @ B[K,N]. SPLIT_OUT=true writes bf16x2 hi/lo planes.
// ---------------------------------------------------------------------------
constexpr int GBM = 128, GBN = 128, GBK = 32;
constexpr int KP  = GBK / 2;
constexpr int ASTR = 20;
constexpr int BSTR = 136;
constexpr int A_STAGE = GBM * ASTR;     // 2560
constexpr int B_STAGE = KP * BSTR;      // 2176
constexpr int GEMM_SMEM_BYTES = 2 * (A_STAGE + B_STAGE) * 4;  // 37888

template <bool SPLIT_OUT>
__global__ __launch_bounds__(256, 2) void gemm_bf16_kernel(
    const float* __restrict__ A, const float* __restrict__ B,
    float* __restrict__ C, uint32_t* __restrict__ Ch, uint32_t* __restrict__ Cl,
    int M, int N, int K)
{
    extern __shared__ uint32_t sm[];
    uint32_t* sAh = sm;
    uint32_t* sAl = sAh + A_STAGE;
    uint32_t* sBh = sAl + A_STAGE;
    uint32_t* sBl = sBh + B_STAGE;

    const int tid  = threadIdx.x;
    const int lane = tid & 31;
    const int wid  = tid >> 5;
    const int m_base = (wid >> 2) * 64;
    const int n_base = (wid & 3) * 32;
    const int row0 = blockIdx.y * GBM;
    const int col0 = blockIdx.x * GBN;

    const int arow  = tid >> 2;
    const int acolg = (tid & 3) * 8;
    const int akp   = (tid & 3) * 4;
    const int brow = tid >> 5;
    const int bcol = (tid & 31) * 4;

    const float* pA0 = A + (size_t)(row0 + arow) * K + acolg;
    const float* pA1 = A + (size_t)(row0 + arow + 64) * K + acolg;
    const float* pB00 = B + (size_t)(2 * brow) * N + col0 + bcol;
    const float* pB01 = B + (size_t)(2 * brow + 1) * N + col0 + bcol;
    const float* pB10 = B + (size_t)(2 * (brow + 8)) * N + col0 + bcol;
    const float* pB11 = B + (size_t)(2 * (brow + 8) + 1) * N + col0 + bcol;

    const int NT = K / GBK;   // 16
    const int gr = lane >> 2;
    const int qc = lane & 3;

    float acc[4][4][4] = {};

    for (int kt = 0; kt < NT; kt++) {
        const int ko = kt * GBK;
        // global loads for this k-tile
        float4 fa00 = *(const float4*)(pA0 + ko);
        float4 fa01 = *(const float4*)(pA0 + ko + 4);
        float4 fa10 = *(const float4*)(pA1 + ko);
        float4 fa11 = *(const float4*)(pA1 + ko + 4);
        float4 fb00 = *(const float4*)(pB00 + (size_t)ko * N);
        float4 fb01 = *(const float4*)(pB01 + (size_t)ko * N);
        float4 fb10 = *(const float4*)(pB10 + (size_t)ko * N);
        float4 fb11 = *(const float4*)(pB11 + (size_t)ko * N);

        if (kt > 0) __syncthreads();   // previous MMA done reading smem

        {   // split + store A rows
            uint32_t h0, l0, h1, l1, h2, l2, h3, l3;
            split2(fa00.x, fa00.y, h0, l0);
            split2(fa00.z, fa00.w, h1, l1);
            split2(fa01.x, fa01.y, h2, l2);
            split2(fa01.z, fa01.w, h3, l3);
            *(uint4*)&sAh[arow * ASTR + akp] = make_uint4(h0, h1, h2, h3);
            *(uint4*)&sAl[arow * ASTR + akp] = make_uint4(l0, l1, l2, l3);
            split2(fa10.x, fa10.y, h0, l0);
            split2(fa10.z, fa10.w, h1, l1);
            split2(fa11.x, fa11.y, h2, l2);
            split2(fa11.z, fa11.w, h3, l3);
            *(uint4*)&sAh[(arow + 64) * ASTR + akp] = make_uint4(h0, h1, h2, h3);
            *(uint4*)&sAl[(arow + 64) * ASTR + akp] = make_uint4(l0, l1, l2, l3);
            // split + store B kp-rows
            split2(fb00.x, fb01.x, h0, l0);
            split2(fb00.y, fb01.y, h1, l1);
            split2(fb00.z, fb01.z, h2, l2);
            split2(fb00.w, fb01.w, h3, l3);
            *(uint4*)&sBh[brow * BSTR + bcol] = make_uint4(h0, h1, h2, h3);
            *(uint4*)&sBl[brow * BSTR + bcol] = make_uint4(l0, l1, l2, l3);
            split2(fb10.x, fb11.x, h0, l0);
            split2(fb10.y, fb11.y, h1, l1);
            split2(fb10.z, fb11.z, h2, l2);
            split2(fb10.w, fb11.w, h3, l3);
            *(uint4*)&sBh[(brow + 8) * BSTR + bcol] = make_uint4(h0, h1, h2, h3);
            *(uint4*)&sBl[(brow + 8) * BSTR + bcol] = make_uint4(l0, l1, l2, l3);
        }
        __syncthreads();

        #pragma unroll
        for (int ks = 0; ks < 2; ks++) {
            const int kp0 = ks * 8 + qc;
            uint32_t ah[4][4], al[4][4], bh[4][2], bl[4][2];
            #pragma unroll
            for (int mt = 0; mt < 4; mt++) {
                const int m = m_base + mt * 16 + gr;
                ah[mt][0] = sAh[m * ASTR + kp0];
                ah[mt][1] = sAh[(m + 8) * ASTR + kp0];
                ah[mt][2] = sAh[m * ASTR + kp0 + 4];
                ah[mt][3] = sAh[(m + 8) * ASTR + kp0 + 4];
                al[mt][0] = sAl[m * ASTR + kp0];
                al[mt][1] = sAl[(m + 8) * ASTR + kp0];
                al[mt][2] = sAl[m * ASTR + kp0 + 4];
                al[mt][3] = sAl[(m + 8) * ASTR + kp0 + 4];
            }
            #pragma unroll
            for (int nt = 0; nt < 4; nt++) {
                const int n = n_base + nt * 8 + gr;
                bh[nt][0] = sBh[kp0 * BSTR + n];
                bh[nt][1] = sBh[(kp0 + 4) * BSTR + n];
                bl[nt][0] = sBl[kp0 * BSTR + n];
                bl[nt][1] = sBl[(kp0 + 4) * BSTR + n];
            }
            #pragma unroll
            for (int mt = 0; mt < 4; mt++)
                #pragma unroll
                for (int nt = 0; nt < 4; nt++) {
                    mma_bf16(acc[mt][nt], ah[mt], bh[nt]);
                    mma_bf16(acc[mt][nt], ah[mt], bl[nt]);
                    mma_bf16(acc[mt][nt], al[mt], bh[nt]);
                }
        }
    }

    #pragma unroll
    for (int mt = 0; mt < 4; mt++) {
        #pragma unroll
        for (int nt = 0; nt < 4; nt++) {
            int r = row0 + m_base + mt * 16 + gr;
            int c = col0 + n_base + nt * 8 + 2 * qc;
            if constexpr (SPLIT_OUT) {
                int kp = c >> 1;
                uint32_t hp, lp;
                split2(acc[mt][nt][0], acc[mt][nt][1], hp, lp);
                Ch[(size_t)r * KPR + kp] = hp;
                Cl[(size_t)r * KPR + kp] = lp;
                split2(acc[mt][nt][2], acc[mt][nt][3], hp, lp);
                Ch[(size_t)(r + 8) * KPR + kp] = hp;
                Cl[(size_t)(r + 8) * KPR + kp] = lp;
            } else {
                *(float2*)&C[(size_t)r * N + c] =
                    make_float2(acc[mt][nt][0], acc[mt][nt][1]);
                *(float2*)&C[(size_t)(r + 8) * N + c] =
                    make_float2(acc[mt][nt][2], acc[mt][nt][3]);
            }
        }
    }
}

// ---------------------------------------------------------------------------
// Attention (R12-validated): split-bf16, ldmatrix, pre-split inputs,
// fixed-max softmax, register-resident P. 256 threads, 6 chunks of 96 keys,
// 2 CTAs/SM.
// ---------------------------------------------------------------------------
constexpr int AQT = 64;
constexpr int AKT = 96;
constexpr int NCHUNK = 6;
constexpr int QSTR2 = 36;
constexpr int KSTR2 = 36;
constexpr int VSTR2 = 52;
constexpr int ATHREADS = 256;
constexpr float FIXM = 12.0f;

constexpr int OFF_QH = 0;
constexpr int OFF_QL = OFF_QH + AQT * QSTR2;
constexpr int OFF_KH = OFF_QL + AQT * QSTR2;
constexpr int OFF_KL = OFF_KH + AKT * KSTR2;
constexpr int OFF_VH = OFF_KL + AKT * KSTR2;
constexpr int OFF_VL = OFF_VH + 64 * VSTR2;
constexpr int OFF_RED = OFF_VL + 64 * VSTR2;
constexpr int OFF_ORED = OFF_RED + 128;
constexpr int ATTN_SMEM_WORDS = OFF_ORED + 64 * 66;
constexpr int ATTN_SMEM_BYTES = ATTN_SMEM_WORDS * 4;  // 90112

__global__ __launch_bounds__(ATHREADS, 2) void attn_tc_kernel()
{
    extern __shared__ uint32_t sm[];
    uint32_t* sQh = sm + OFF_QH;
    uint32_t* sQl = sm + OFF_QL;
    uint32_t* sKh = sm + OFF_KH;
    uint32_t* sKl = sm + OFF_KL;
    uint32_t* sVh = sm + OFF_VH;
    uint32_t* sVl = sm + OFF_VL;
    float* red  = (float*)(sm + OFF_RED);
    float* ored = (float*)(sm + OFF_ORED);

    const int tid  = threadIdx.x;
    const int lane = tid & 31;
    const int wid  = tid >> 5;
    const int gr = lane >> 2;
    const int qc = lane & 3;
    const int wm = wid >> 1;
    const int wn = wid & 1;
    const int m0 = wm * 16;

    const int t0 = blockIdx.x * AQT;
    const int h  = blockIdx.y;
    const int b  = blockIdx.z;
    const float slope = exp2f(-(float)(h + 1));

    const uint32_t* Qh_p = g_qh + ((size_t)(b * S_LEN + t0)) * KPR + h * 32;
    const uint32_t* Ql_p = g_ql + ((size_t)(b * S_LEN + t0)) * KPR + h * 32;
    const uint32_t* Kh_p = g_kh + ((size_t)b * S_LEN) * KPR + h * 32;
    const uint32_t* Kl_p = g_kl + ((size_t)b * S_LEN) * KPR + h * 32;
    const uint32_t* Vh_p = g_vh + ((size_t)b * S_LEN) * KPR + h * 32;
    const uint32_t* Vl_p = g_vl + ((size_t)b * S_LEN) * KPR + h * 32;
    float* Ob = g_att + (size_t)b * S_LEN * EMB + h * DH;

    const int lrow8  = (lane & 7);
    const int lmsel  = (lane >> 3) & 1;
    const int lhsel  = (lane >> 4) & 1;

    const uint32_t qh_base = smem_u32(sQh) +
        (((m0 + lrow8 + lmsel * 8) * QSTR2) + lhsel * 4) * 4;
    const uint32_t ql_base = qh_base + (OFF_QL - OFF_QH) * 4;
    const int nbase = wn * 48;
    const uint32_t kh_base = smem_u32(sKh) +
        (((nbase + lrow8 + lhsel * 8) * KSTR2) + lmsel * 4) * 4;
    const uint32_t kl_base = kh_base + (OFF_KL - OFF_KH) * 4;
    const uint32_t vh_base = smem_u32(sVh) +
        (((lrow8 + lhsel * 8) * VSTR2) + wn * 24 + lmsel * 4) * 4;
    const uint32_t vl_base = vh_base + (OFF_VL - OFF_VH) * 4;

    for (int idx = tid; idx < 512; idx += ATHREADS) {
        int q = idx >> 3;
        int j = idx & 7;
        uint4 vh = *(const uint4*)&Qh_p[(size_t)q * KPR + j * 4];
        uint4 vl = *(const uint4*)&Ql_p[(size_t)q * KPR + j * 4];
        *(uint4*)&sQh[q * QSTR2 + j * 4] = vh;
        *(uint4*)&sQl[q * QSTR2 + j * 4] = vl;
    }

    float o[8][4] = {};
    float sum0 = 0.f, sum1 = 0.f;

    const int base = t0 - HALF;

    #pragma unroll 1
    for (int c = 0; c < NCHUNK; c++) {
        const int cs = base + c * AKT;
        if (cs + AKT <= 0 || cs >= S_LEN) continue;

        for (int idx = tid; idx < 768; idx += ATHREADS) {
            int key = idx >> 3;
            int j = idx & 7;
            int T = cs + key;
            uint4 vh = make_uint4(0, 0, 0, 0);
            uint4 vl = make_uint4(0, 0, 0, 0);
            if (T >= 0 && T < S_LEN) {
                vh = *(const uint4*)&Kh_p[(size_t)T * KPR + j * 4];
                vl = *(const uint4*)&Kl_p[(size_t)T * KPR + j * 4];
            }
            *(uint4*)&sKh[key * KSTR2 + j * 4] = vh;
            *(uint4*)&sKl[key * KSTR2 + j * 4] = vl;
        }
        for (int idx = tid; idx < 384; idx += ATHREADS) {
            int kp = idx >> 3;
            int j = idx & 7;
            int T0 = cs + 2 * kp, T1 = T0 + 1;
            uint4 ah = make_uint4(0, 0, 0, 0), al = make_uint4(0, 0, 0, 0);
            uint4 bh = make_uint4(0, 0, 0, 0), bl = make_uint4(0, 0, 0, 0);
            if (T0 >= 0 && T0 < S_LEN) {
                ah = *(const uint4*)&Vh_p[(size_t)T0 * KPR + j * 4];
                al = *(const uint4*)&Vl_p[(size_t)T0 * KPR + j * 4];
            }
            if (T1 >= 0 && T1 < S_LEN) {
                bh = *(const uint4*)&Vh_p[(size_t)T1 * KPR + j * 4];
                bl = *(const uint4*)&Vl_p[(size_t)T1 * KPR + j * 4];
            }
            int d0 = 8 * j;
            sVh[(d0 + 0) * VSTR2 + kp] = prmt(ah.x, bh.x, 0x5410);
            sVh[(d0 + 1) * VSTR2 + kp] = prmt(ah.x, bh.x, 0x7632);
            sVh[(d0 + 2) * VSTR2 + kp] = prmt(ah.y, bh.y, 0x5410);
            sVh[(d0 + 3) * VSTR2 + kp] = prmt(ah.y, bh.y, 0x7632);
            sVh[(d0 + 4) * VSTR2 + kp] = prmt(ah.z, bh.z, 0x5410);
            sVh[(d0 + 5) * VSTR2 + kp] = prmt(ah.z, bh.z, 0x7632);
            sVh[(d0 + 6) * VSTR2 + kp] = prmt(ah.w, bh.w, 0x5410);
            sVh[(d0 + 7) * VSTR2 + kp] = prmt(ah.w, bh.w, 0x7632);
            sVl[(d0 + 0) * VSTR2 + kp] = prmt(al.x, bl.x, 0x5410);
            sVl[(d0 + 1) * VSTR2 + kp] = prmt(al.x, bl.x, 0x7632);
            sVl[(d0 + 2) * VSTR2 + kp] = prmt(al.y, bl.y, 0x5410);
            sVl[(d0 + 3) * VSTR2 + kp] = prmt(al.y, bl.y, 0x7632);
            sVl[(d0 + 4) * VSTR2 + kp] = prmt(al.z, bl.z, 0x5410);
            sVl[(d0 + 5) * VSTR2 + kp] = prmt(al.z, bl.z, 0x7632);
            sVl[(d0 + 6) * VSTR2 + kp] = prmt(al.w, bl.w, 0x5410);
            sVl[(d0 + 7) * VSTR2 + kp] = prmt(al.w, bl.w, 0x7632);
        }
        __syncthreads();

        float s[6][4];
        #pragma unroll
        for (int nt = 0; nt < 6; nt++)
            #pragma unroll
            for (int i = 0; i < 4; i++) s[nt][i] = 0.f;

        #pragma unroll
        for (int ks = 0; ks < 4; ks++) {
            uint32_t ah[4], al[4];
            ldsm_x4(ah, qh_base + ks * 32);
            ldsm_x4(al, ql_base + ks * 32);
            #pragma unroll
            for (int ntp = 0; ntp < 3; ntp++) {
                uint32_t bh[4], bl[4];
                ldsm_x4(bh, kh_base + ks * 32 + ntp * (16 * KSTR2 * 4));
                ldsm_x4(bl, kl_base + ks * 32 + ntp * (16 * KSTR2 * 4));
                mma_bf16(s[2 * ntp],     ah, bh);
                mma_bf16(s[2 * ntp],     ah, bl);
                mma_bf16(s[2 * ntp],     al, bh);
                mma_bf16(s[2 * ntp + 1], ah, bh + 2);
                mma_bf16(s[2 * ntp + 1], ah, bl + 2);
                mma_bf16(s[2 * ntp + 1], al, bh + 2);
            }
        }

        const int trow0 = t0 + m0 + gr;
        const int trow1 = trow0 + 8;
        uint32_t pah[3][4], pal[3][4];
        #pragma unroll
        for (int nt = 0; nt < 6; nt++) {
            int T0 = cs + nbase + nt * 8 + 2 * qc;
            int T1 = T0 + 1;
            bool in0 = (T0 >= 0) && (T0 < S_LEN);
            bool in1 = (T1 >= 0) && (T1 < S_LEN);
            int a00 = abs(trow0 - T0), a01 = abs(trow0 - T1);
            int a10 = abs(trow1 - T0), a11 = abs(trow1 - T1);
            float p00 = (in0 && a00 <= HALF)
                ? __expf(fmaf(s[nt][0], 0.125f, fmaf(-slope, (float)a00, -FIXM))) : 0.f;
            float p01 = (in1 && a01 <= HALF)
                ? __expf(fmaf(s[nt][1], 0.125f, fmaf(-slope, (float)a01, -FIXM))) : 0.f;
            float p10 = (in0 && a10 <= HALF)
                ? __expf(fmaf(s[nt][2], 0.125f, fmaf(-slope, (float)a10, -FIXM))) : 0.f;
            float p11 = (in1 && a11 <= HALF)
                ? __expf(fmaf(s[nt][3], 0.125f, fmaf(-slope, (float)a11, -FIXM))) : 0.f;
            sum0 += p00 + p01;
            sum1 += p10 + p11;
            int ks = nt >> 1;
            int half = (nt & 1) * 2;
            uint32_t hp, lp;
            split2(p00, p01, hp, lp);
            pah[ks][half + 0] = hp;  pal[ks][half + 0] = lp;
            split2(p10, p11, hp, lp);
            pah[ks][half + 1] = hp;  pal[ks][half + 1] = lp;
        }

        #pragma unroll
        for (int ks = 0; ks < 3; ks++) {
            #pragma unroll
            for (int dt = 0; dt < 4; dt++) {
                uint32_t bh[4], bl[4];
                uint32_t off = (uint32_t)(dt * 16 * VSTR2 * 4 + ks * 32);
                ldsm_x4(bh, vh_base + off);
                ldsm_x4(bl, vl_base + off);
                mma_bf16(o[2 * dt],     pah[ks], bh);
                mma_bf16(o[2 * dt],     pah[ks], bl);
                mma_bf16(o[2 * dt],     pal[ks], bh);
                mma_bf16(o[2 * dt + 1], pah[ks], bh + 2);
                mma_bf16(o[2 * dt + 1], pah[ks], bl + 2);
                mma_bf16(o[2 * dt + 1], pal[ks], bh + 2);
            }
        }
        __syncthreads();
    }

    sum0 += __shfl_xor_sync(0xffffffffu, sum0, 1);
    sum0 += __shfl_xor_sync(0xffffffffu, sum0, 2);
    sum1 += __shfl_xor_sync(0xffffffffu, sum1, 1);
    sum1 += __shfl_xor_sync(0xffffffffu, sum1, 2);
    if (qc == 0) {
        red[(m0 + gr) * 2 + wn] = sum0;
        red[(m0 + gr + 8) * 2 + wn] = sum1;
    }
    if (wn == 1) {
        #pragma unroll
        for (int nt = 0; nt < 8; nt++) {
            int d = nt * 8 + 2 * qc;
            *(float2*)&ored[(m0 + gr) * 66 + d] = make_float2(o[nt][0], o[nt][1]);
            *(float2*)&ored[(m0 + gr + 8) * 66 + d] = make_float2(o[nt][2], o[nt][3]);
        }
    }
    __syncthreads();

    if (wn == 0) {
        const int trow0 = t0 + m0 + gr;
        const float inv0 = 1.0f / (red[(m0 + gr) * 2] + red[(m0 + gr) * 2 + 1]);
        const float inv1 = 1.0f / (red[(m0 + gr + 8) * 2] + red[(m0 + gr + 8) * 2 + 1]);
        #pragma unroll
        for (int nt = 0; nt < 8; nt++) {
            int d = nt * 8 + 2 * qc;
            float2 p0 = *(float2*)&ored[(m0 + gr) * 66 + d];
            float2 p1 = *(float2*)&ored[(m0 + gr + 8) * 66 + d];
            *(float2*)&Ob[(size_t)trow0 * EMB + d] =
                make_float2((o[nt][0] + p0.x) * inv0, (o[nt][1] + p0.y) * inv0);
            *(float2*)&Ob[(size_t)(trow0 + 8) * EMB + d] =
                make_float2((o[nt][2] + p1.x) * inv1, (o[nt][3] + p1.y) * inv1);
        }
    }
}

// ---------------------------------------------------------------------------
extern "C" void kernel_launch(void* const* d_in, const int* in_sizes, int n_in,
                              void* d_out, int out_size)
{
    (void)in_sizes; (void)n_in; (void)out_size;
    const float* inputs_q  = (const float*)d_in[0];
    const float* inputs_kv = (const float*)d_in[1];
    const float* w_q = (const float*)d_in[2];
    const float* w_k = (const float*)d_in[3];
    const float* w_v = (const float*)d_in[4];
    const float* w_o = (const float*)d_in[5];
    float* out = (float*)d_out;

    uint32_t *qh, *ql, *kh, *kl, *vh, *vl;
    float* ab;
    cudaGetSymbolAddress((void**)&qh, g_qh);
    cudaGetSymbolAddress((void**)&ql, g_ql);
    cudaGetSymbolAddress((void**)&kh, g_kh);
    cudaGetSymbolAddress((void**)&kl, g_kl);
    cudaGetSymbolAddress((void**)&vh, g_vh);
    cudaGetSymbolAddress((void**)&vl, g_vl);
    cudaGetSymbolAddress((void**)&ab, g_att);

    cudaFuncSetAttribute(gemm_bf16_kernel<true>,
                         cudaFuncAttributeMaxDynamicSharedMemorySize,
                         GEMM_SMEM_BYTES);
    cudaFuncSetAttribute(gemm_bf16_kernel<false>,
                         cudaFuncAttributeMaxDynamicSharedMemorySize,
                         GEMM_SMEM_BYTES);
    cudaFuncSetAttribute(attn_tc_kernel,
                         cudaFuncAttributeMaxDynamicSharedMemorySize,
                         ATTN_SMEM_BYTES);

    dim3 gGemm(EMB / GBN, ROWS / GBM);   // (4, 64) = 256 CTAs, 1 wave @ 2/SM
    gemm_bf16_kernel<true><<<gGemm, 256, GEMM_SMEM_BYTES>>>(
        inputs_q,  w_q, nullptr, qh, ql, ROWS, EMB, EMB);
    gemm_bf16_kernel<true><<<gGemm, 256, GEMM_SMEM_BYTES>>>(
        inputs_kv, w_k, nullptr, kh, kl, ROWS, EMB, EMB);
    gemm_bf16_kernel<true><<<gGemm, 256, GEMM_SMEM_BYTES>>>(
        inputs_kv, w_v, nullptr, vh, vl, ROWS, EMB, EMB);

    dim3 gAttn(S_LEN / AQT, NH, BATCH);  // (64, 8, 2)
    attn_tc_kernel<<<gAttn, ATHREADS, ATTN_SMEM_BYTES>>>();

    gemm_bf16_kernel<false><<<gGemm, 256, GEMM_SMEM_BYTES>>>(
        ab, w_o, out, nullptr, nullptr, ROWS, EMB, EMB);
}